// round 13
// baseline (speedup 1.0000x reference)
#include <cuda_runtime.h>
#include <cuda_fp16.h>
#include <mma.h>
#include <math.h>

using namespace nvcuda;

#define NB 8
#define NF 128
#define LATD 256
#define NPIX 4096
#define NCALLS 16
#define FIN 384
#define KT 197376

#define OFF_WIN  0
#define OFF_BIN  49152
#define OFF_WMID 49280
#define OFF_BMID 65664
#define OFF_WOUT 65792
#define OFF_BOUT 98560
#define OFF_WSH  98816
#define OFF_BSH  197120

#define COLSZ 4718592   // 1152 * 4096 (NOT a power of 2 — true division!)

// -------- scratch --------
__device__ __align__(16) float g_kall[NB * KT];
__device__ __align__(16) __half g_pf [NB * FIN * NPIX];
__device__ __align__(16) __half g_w1h[NB * 128 * 384], g_w1l[NB * 128 * 384];
__device__ __align__(16) __half g_w2h[NB * 128 * 128], g_w2l[NB * 128 * 128];
__device__ __align__(16) __half g_w3h[NB * 256 * 512], g_w3l[NB * 256 * 512];
__device__ __align__(16) __half g_colf[NB * 1152 * NPIX];
__device__ __align__(16) __half g_rw1h[NB * 147456], g_rw1l[NB * 147456];
__device__ __align__(16) __half g_rw2h[NB * 147456], g_rw2l[NB * 147456];
__device__ __align__(16) float g_c2[NB * NF * NPIX];

#define CP16(dst, src) \
    asm volatile("cp.async.cg.shared.global [%0], [%1], 16;\n" :: "r"(dst), "l"(src))
#define CP_COMMIT() asm volatile("cp.async.commit_group;\n" ::: "memory")
#define CP_WAIT(n)  asm volatile("cp.async.wait_group %0;\n" :: "n"(n) : "memory")

__device__ __forceinline__ void splitA(float v, __half& h, __half& l) {
    h = __float2half_rn(v);
    l = __float2half_rn(v - __half2float(h));
}

// ======================================================================
// hyper + pack fused
// ======================================================================
__global__ void __launch_bounds__(256) hyper_kernel(
    const float* __restrict__ lat, const float* __restrict__ hw,
    const float* __restrict__ hb, float* __restrict__ kall)
{
    __shared__ float ls[NB * LATD];
    const int tid = threadIdx.x;
    for (int i = tid; i < NB * LATD; i += 256) ls[i] = lat[i];
    __syncthreads();
    const int n = blockIdx.x * 256 + tid;
    float acc[NB];
#pragma unroll
    for (int b = 0; b < NB; b++) acc[b] = 0.f;
    for (int k = 0; k < LATD; k++) {
        float w = hw[(size_t)k * KT + n];
#pragma unroll
        for (int b = 0; b < NB; b++) acc[b] = fmaf(ls[b * LATD + k], w, acc[b]);
    }
    const float bias = hb[n];

    float s = 1.f;
    int kind;
    size_t widx = 0;
    if (n < OFF_BIN)       { s = 0.05103103630798288f; kind = 0; widx = n; }
    else if (n < OFF_WMID) { kind = 3; }
    else if (n < OFF_BMID) { s = 0.08838834764831845f; kind = 1; widx = n - OFF_WMID; }
    else if (n < OFF_WOUT) { kind = 3; }
    else if (n < OFF_BOUT) {
        s = 0.08838834764831845f; kind = 2;
        int i = n - OFF_WOUT;
        widx = (size_t)(i >> 7) * 512 + (i & 127);
    } else if (n < OFF_WSH) { kind = 3; }
    else if (n < OFF_BSH) {
        s = 0.05103103630798288f; kind = 2;
        int i = n - OFF_WSH;
        widx = (size_t)(i / 384) * 512 + 128 + (i % 384);
    } else kind = 3;

#pragma unroll
    for (int b = 0; b < NB; b++) {
        float v = (acc[b] + bias) * s;
        if (kind == 3) {
            kall[(size_t)b * KT + n] = v;
        } else {
            __half h, l;
            splitA(v, h, l);
            if (kind == 0)      { g_w1h[(size_t)b * 49152 + widx] = h;  g_w1l[(size_t)b * 49152 + widx] = l; }
            else if (kind == 1) { g_w2h[(size_t)b * 16384 + widx] = h;  g_w2l[(size_t)b * 16384 + widx] = l; }
            else                { g_w3h[(size_t)b * 131072 + widx] = h; g_w3l[(size_t)b * 131072 + widx] = l; }
        }
    }
}

// ======================================================================
// pack res-conv weights
// ======================================================================
__global__ void __launch_bounds__(256) pack_rw_kernel(
    const float* __restrict__ w, __half* __restrict__ dh, __half* __restrict__ dl)
{
    const int idx = blockIdx.x * 256 + threadIdx.x;
    const int o = idx / 1152, r = idx - o * 1152;
    const int t = r >> 7, c = r & 127;
    float v = w[o * 1152 + c * 9 + t];
    __half h, l;
    splitA(v, h, l);
#pragma unroll
    for (int b = 0; b < NB; b++) {
        dh[(size_t)b * 147456 + idx] = h;
        dl[(size_t)b * 147456 + idx] = l;
    }
}

// ======================================================================
// im2col
// ======================================================================
__global__ void __launch_bounds__(256) im2col_f32_kernel(
    const float* __restrict__ src, __half* __restrict__ d)
{
    const size_t idx = (size_t)blockIdx.x * 256 + threadIdx.x;
    const int b = (int)(idx / COLSZ);
    const size_t r = idx - (size_t)b * COLSZ;
    const int k = (int)(r >> 12), px = (int)(r & 4095);
    const int tap = k >> 7, ch = k & 127;
    const int dy = tap / 3 - 1, dx = tap % 3 - 1;
    const int y = (px >> 6) + dy, x = (px & 63) + dx;
    float v = 0.f;
    if ((unsigned)y < 64u && (unsigned)x < 64u)
        v = src[(((size_t)b * 128 + ch) << 12) + y * 64 + x];
    d[idx] = __float2half_rn(v);
}

__global__ void __launch_bounds__(256) im2col_h_kernel(
    const __half* __restrict__ src, __half* __restrict__ d)
{
    const size_t idx = (size_t)blockIdx.x * 256 + threadIdx.x;
    const int b = (int)(idx / COLSZ);
    const size_t r = idx - (size_t)b * COLSZ;
    const int k = (int)(r >> 12), px = (int)(r & 4095);
    const int tap = k >> 7, ch = k & 127;
    const int dy = tap / 3 - 1, dx = tap % 3 - 1;
    const int y = (px >> 6) + dy, x = (px & 63) + dx;
    __half v = __float2half_rn(0.f);
    if ((unsigned)y < 64u && (unsigned)x < 64u)
        v = src[(((size_t)b * 128 + ch) << 12) + y * 64 + x];
    d[idx] = v;
}

// ======================================================================
// build_p -> single fp16 plane
// ======================================================================
__global__ void __launch_bounds__(256) build_p_kernel(
    const float* __restrict__ X, __half* __restrict__ P)
{
    const int c = blockIdx.x, b = blockIdx.y, tid = threadIdx.x;
    __shared__ float sp[68 * 68];
    __shared__ float red[8][6];
    __shared__ float stats[6];
    for (int i = tid; i < 68 * 68; i += 256) sp[i] = 0.f;
    __syncthreads();
    const float* Xp = X + ((size_t)b * NF + c) * NPIX;
    for (int i = tid; i < NPIX; i += 256) {
        int y = i >> 6, x = i & 63;
        sp[(y + 2) * 68 + (x + 2)] = Xp[i];
    }
    __syncthreads();
    const float C = 0.70710678118654752f;
    float vx[16], vsx[16], vsy[16];
    float s0 = 0.f, q0 = 0.f, s1 = 0.f, q1 = 0.f, s2 = 0.f, q2 = 0.f;
#pragma unroll
    for (int it = 0; it < 16; it++) {
        int pix = tid + it * 256;
        int y = pix >> 6, x = pix & 63;
        const float* B = &sp[y * 68 + x];
        float xv = B[2*68+2];
        float sx = C*(B[1*68+4]-B[1*68+0]) + 0.5f*(B[1*68+3]-B[1*68+1])
                 + (B[2*68+4]-B[2*68+0]) + C*(B[2*68+3]-B[2*68+1])
                 + C*(B[3*68+4]-B[3*68+0]) + 0.5f*(B[3*68+3]-B[3*68+1]);
        float sy = C*(B[4*68+1]-B[0*68+1]) + (B[4*68+2]-B[0*68+2])
                 + C*(B[4*68+3]-B[0*68+3])
                 + 0.5f*(B[3*68+1]-B[1*68+1]) + C*(B[3*68+2]-B[1*68+2])
                 + 0.5f*(B[3*68+3]-B[1*68+3]);
        vx[it] = xv; vsx[it] = sx; vsy[it] = sy;
        s0 += xv; q0 = fmaf(xv, xv, q0);
        s1 += sx; q1 = fmaf(sx, sx, q1);
        s2 += sy; q2 = fmaf(sy, sy, q2);
    }
#pragma unroll
    for (int off = 16; off; off >>= 1) {
        s0 += __shfl_down_sync(~0u, s0, off); q0 += __shfl_down_sync(~0u, q0, off);
        s1 += __shfl_down_sync(~0u, s1, off); q1 += __shfl_down_sync(~0u, q1, off);
        s2 += __shfl_down_sync(~0u, s2, off); q2 += __shfl_down_sync(~0u, q2, off);
    }
    if ((tid & 31) == 0) {
        int w = tid >> 5;
        red[w][0]=s0; red[w][1]=q0; red[w][2]=s1; red[w][3]=q1; red[w][4]=s2; red[w][5]=q2;
    }
    __syncthreads();
    if (tid == 0) {
        float S[6] = {0,0,0,0,0,0};
        for (int w = 0; w < 8; w++) for (int j = 0; j < 6; j++) S[j] += red[w][j];
        const float invN = 1.f / 4096.f;
#pragma unroll
        for (int t3 = 0; t3 < 3; t3++) {
            float mu = S[2*t3] * invN;
            float var = fmaxf(S[2*t3+1] * invN - mu*mu, 0.f);
            stats[2*t3] = mu; stats[2*t3+1] = rsqrtf(var + 1e-5f);
        }
    }
    __syncthreads();
    const float mu0 = stats[0], in0 = stats[1], mu1 = stats[2], in1 = stats[3],
                mu2 = stats[4], in2 = stats[5];
    const size_t p0 = ((size_t)b * FIN + c) * NPIX;
#pragma unroll
    for (int it = 0; it < 16; it++) {
        int pix = tid + it * 256;
        P[p0 + pix]                      = __float2half_rn((vx[it]  - mu0) * in0);
        P[p0 + (size_t)NF*NPIX + pix]    = __float2half_rn((vsx[it] - mu1) * in1);
        P[p0 + (size_t)2*NF*NPIX + pix]  = __float2half_rn((vsy[it] - mu2) * in2);
    }
}

// ======================================================================
// FULL STEP GEMM: h1 = relu(W1@p+b1); h2 = relu(W2@h1+b2) [both in smem];
// dn = W3 @ [h2; p] + biases; xn = x + leak*val*sigmoid(gate).
// CTA = 128 pixels. smem: region A [0, 69632) = stages/Es; H at 69632.
// ======================================================================
__global__ void __launch_bounds__(256, 2) step_kernel(
    const __half* __restrict__ W1h, const __half* __restrict__ W1l,
    const __half* __restrict__ W2h, const __half* __restrict__ W2l,
    const __half* __restrict__ W3h, const __half* __restrict__ W3l,
    const __half* __restrict__ P, const float* __restrict__ kall,
    const float* __restrict__ xold, float* __restrict__ xnew,
    const float* __restrict__ leakp)
{
    constexpr int KCH = 16;
    constexpr int AW = 24;           // 48B rows
    constexpr int BW = 136;          // phase1/2 B + H rows (272B)
    constexpr int BW3 = 72;          // phase3 p rows (144B)
    constexpr int EW = 132;          // phase1/2 Es
    constexpr int EW3 = 68;          // phase3 Es
    constexpr int A1 = 128 * AW;                    // 3072 halfs/plane (128-row A)
    constexpr int A3 = 256 * AW;                    // 6144 halfs/plane (256-row A)
    constexpr int BUF1 = 2 * A1 + KCH * BW;         // 8320 halfs
    constexpr int BUF2 = 2 * A1;                    // 6144
    constexpr int BUF3 = 2 * A3 + KCH * BW3;        // 13440 halfs = 26880 B

    extern __shared__ __align__(16) char sm[];
    __half* smA = (__half*)sm;                      // region A (stages / Es alias)
    float* Es = (float*)sm;
    __half* H = (__half*)(sm + 69632);              // 128 x 136 fp16

    const int tid = threadIdx.x;
    const int b = blockIdx.y;
    const int n0 = blockIdx.x * 128;
    const int wid = tid >> 5;
    const int wm = wid >> 1, wn = wid & 1;

    const __half* W1hB = W1h + (size_t)b * 49152;
    const __half* W1lB = W1l + (size_t)b * 49152;
    const __half* W2hB = W2h + (size_t)b * 16384;
    const __half* W2lB = W2l + (size_t)b * 16384;
    const __half* W3hB = W3h + (size_t)b * 131072;
    const __half* W3lB = W3l + (size_t)b * 131072;
    const __half* Pb = P + (size_t)b * FIN * NPIX;

    wmma::fragment<wmma::accumulator, 16, 16, 16, float> acc[2][4];
#pragma unroll
    for (int i = 0; i < 2; i++)
#pragma unroll
        for (int j = 0; j < 4; j++) wmma::fill_fragment(acc[i][j], 0.f);

    // ---------------- phase 1: h1 = relu(W1 @ p + b1) ----------------
    auto stage1 = [&](int kc, int s) {
        __half* Ah = smA + (size_t)s * BUF1;
        __half* Al = Ah + A1;
        __half* Bf = Al + A1;
#pragma unroll
        for (int i = tid; i < 512; i += 256) {
            int plane = (i >= 256);
            int rem = i - plane * 256;
            int m = rem >> 1, q = rem & 1;
            const __half* src = (plane ? W1lB : W1hB) + (size_t)m * 384 + kc + q * 8;
            unsigned d = (unsigned)__cvta_generic_to_shared(
                (plane ? Al : Ah) + m * AW + q * 8);
            CP16(d, src);
        }
        {
            int k = tid >> 4, c = (tid & 15) * 8;
            const __half* src = Pb + (size_t)(kc + k) * NPIX + n0 + c;
            unsigned d = (unsigned)__cvta_generic_to_shared(Bf + k * BW + c);
            CP16(d, src);
        }
        CP_COMMIT();
    };
    auto compute1 = [&](int s) {
        const __half* Ah = smA + (size_t)s * BUF1;
        const __half* Al = Ah + A1;
        const __half* Bf = Al + A1;
        wmma::fragment<wmma::matrix_a, 16, 16, 16, __half, wmma::row_major> ah[2], al[2];
        wmma::fragment<wmma::matrix_b, 16, 16, 16, __half, wmma::row_major> bf[4];
#pragma unroll
        for (int i = 0; i < 2; i++) {
            wmma::load_matrix_sync(ah[i], Ah + (wm * 32 + i * 16) * AW, AW);
            wmma::load_matrix_sync(al[i], Al + (wm * 32 + i * 16) * AW, AW);
        }
#pragma unroll
        for (int j = 0; j < 4; j++)
            wmma::load_matrix_sync(bf[j], Bf + wn * 64 + j * 16, BW);
#pragma unroll
        for (int i = 0; i < 2; i++)
#pragma unroll
            for (int j = 0; j < 4; j++) {
                wmma::mma_sync(acc[i][j], ah[i], bf[j], acc[i][j]);
                wmma::mma_sync(acc[i][j], al[i], bf[j], acc[i][j]);
            }
    };

    {
        const int nch = 24;
        stage1(0, 0);
        stage1(KCH, 1);
        CP_WAIT(1);
        __syncthreads();
        for (int ic = 0; ic < nch; ic++) {
            compute1(ic % 3);
            if (ic + 2 < nch) {
                stage1((ic + 2) * KCH, (ic + 2) % 3);
                CP_WAIT(1);
            } else {
                CP_WAIT(0);
            }
            __syncthreads();
        }
    }
#pragma unroll
    for (int i = 0; i < 2; i++)
#pragma unroll
        for (int j = 0; j < 4; j++)
            wmma::store_matrix_sync(Es + (wm * 32 + i * 16) * EW + wn * 64 + j * 16,
                                    acc[i][j], EW, wmma::mem_row_major);
    __syncthreads();
    {
        const int m = tid >> 1, seg = tid & 1;
        const float bias1 = kall[(size_t)b * KT + OFF_BIN + m];
        const float* er = Es + m * EW + seg * 64;
        __half* hr = H + m * BW + seg * 64;
#pragma unroll
        for (int c = 0; c < 64; c += 2) {
            __half2 o;
            o.x = __float2half_rn(fmaxf(er[c + 0] + bias1, 0.f));
            o.y = __float2half_rn(fmaxf(er[c + 1] + bias1, 0.f));
            *reinterpret_cast<__half2*>(&hr[c]) = o;
        }
    }
    __syncthreads();

    // ---------------- phase 2: h2 = relu(W2 @ h1 + b2), h1 in H ----------------
#pragma unroll
    for (int i = 0; i < 2; i++)
#pragma unroll
        for (int j = 0; j < 4; j++) wmma::fill_fragment(acc[i][j], 0.f);

    auto stage2 = [&](int kc, int s) {
        __half* Ah = smA + (size_t)s * BUF2;
        __half* Al = Ah + A1;
#pragma unroll
        for (int i = tid; i < 512; i += 256) {
            int plane = (i >= 256);
            int rem = i - plane * 256;
            int m = rem >> 1, q = rem & 1;
            const __half* src = (plane ? W2lB : W2hB) + (size_t)m * 128 + kc + q * 8;
            unsigned d = (unsigned)__cvta_generic_to_shared(
                (plane ? Al : Ah) + m * AW + q * 8);
            CP16(d, src);
        }
        CP_COMMIT();
    };
    auto compute2 = [&](int kc, int s) {
        const __half* Ah = smA + (size_t)s * BUF2;
        const __half* Al = Ah + A1;
        wmma::fragment<wmma::matrix_a, 16, 16, 16, __half, wmma::row_major> ah[2], al[2];
        wmma::fragment<wmma::matrix_b, 16, 16, 16, __half, wmma::row_major> bf[4];
#pragma unroll
        for (int i = 0; i < 2; i++) {
            wmma::load_matrix_sync(ah[i], Ah + (wm * 32 + i * 16) * AW, AW);
            wmma::load_matrix_sync(al[i], Al + (wm * 32 + i * 16) * AW, AW);
        }
#pragma unroll
        for (int j = 0; j < 4; j++)
            wmma::load_matrix_sync(bf[j], H + kc * BW + wn * 64 + j * 16, BW);
#pragma unroll
        for (int i = 0; i < 2; i++)
#pragma unroll
            for (int j = 0; j < 4; j++) {
                wmma::mma_sync(acc[i][j], ah[i], bf[j], acc[i][j]);
                wmma::mma_sync(acc[i][j], al[i], bf[j], acc[i][j]);
            }
    };

    {
        const int nch = 8;
        stage2(0, 0);
        stage2(KCH, 1);
        CP_WAIT(1);
        __syncthreads();
        for (int ic = 0; ic < nch; ic++) {
            compute2(ic * KCH, ic % 3);
            if (ic + 2 < nch) {
                stage2((ic + 2) * KCH, (ic + 2) % 3);
                CP_WAIT(1);
            } else {
                CP_WAIT(0);
            }
            __syncthreads();
        }
    }
#pragma unroll
    for (int i = 0; i < 2; i++)
#pragma unroll
        for (int j = 0; j < 4; j++)
            wmma::store_matrix_sync(Es + (wm * 32 + i * 16) * EW + wn * 64 + j * 16,
                                    acc[i][j], EW, wmma::mem_row_major);
    __syncthreads();
    {
        // h2 -> H (overwrites h1; all phase-2 reads done)
        const int m = tid >> 1, seg = tid & 1;
        const float bias2 = kall[(size_t)b * KT + OFF_BMID + m];
        const float* er = Es + m * EW + seg * 64;
        __half* hr = H + m * BW + seg * 64;
#pragma unroll
        for (int c = 0; c < 64; c += 2) {
            __half2 o;
            o.x = __float2half_rn(fmaxf(er[c + 0] + bias2, 0.f));
            o.y = __float2half_rn(fmaxf(er[c + 1] + bias2, 0.f));
            *reinterpret_cast<__half2*>(&hr[c]) = o;
        }
    }
    __syncthreads();

    // ------------- phase 3: dn = W3 @ [h2; p], two 64-px halves -------------
    const float leak = fminf(fmaxf(leakp[0], 0.001f), 1000.f);
    const float* ka = kall + (size_t)b * KT;

    auto stage3 = [&](int kc, int s, int hh) {
        __half* Ah = smA + (size_t)s * BUF3;
        __half* Al = Ah + A3;
        __half* Bp = Al + A3;
#pragma unroll
        for (int i = tid; i < 1024; i += 256) {
            int plane = (i >= 512);
            int rem = i - plane * 512;
            int m = rem >> 1, q = rem & 1;
            const __half* src = (plane ? W3lB : W3hB) + (size_t)m * 512 + kc + q * 8;
            unsigned d = (unsigned)__cvta_generic_to_shared(
                (plane ? Al : Ah) + m * AW + q * 8);
            CP16(d, src);
        }
        if (kc >= 128 && tid < 128) {
            int k = tid >> 3, c = (tid & 7) * 8;
            const __half* src = Pb + (size_t)(kc - 128 + k) * NPIX + n0 + hh * 64 + c;
            unsigned d = (unsigned)__cvta_generic_to_shared(Bp + k * BW3 + c);
            CP16(d, src);
        }
        CP_COMMIT();
    };
    auto compute3 = [&](int kc, int s, int hh) {
        const __half* Ah = smA + (size_t)s * BUF3;
        const __half* Al = Ah + A3;
        const __half* Bp = Al + A3;
        wmma::fragment<wmma::matrix_a, 16, 16, 16, __half, wmma::row_major> ah[2], al[2];
        wmma::fragment<wmma::matrix_b, 16, 16, 16, __half, wmma::row_major> bf[4];
#pragma unroll
        for (int i = 0; i < 2; i++) {
            wmma::load_matrix_sync(ah[i], Ah + (wid * 32 + i * 16) * AW, AW);
            wmma::load_matrix_sync(al[i], Al + (wid * 32 + i * 16) * AW, AW);
        }
        if (kc < 128) {
#pragma unroll
            for (int j = 0; j < 4; j++)
                wmma::load_matrix_sync(bf[j], H + kc * BW + hh * 64 + j * 16, BW);
        } else {
#pragma unroll
            for (int j = 0; j < 4; j++)
                wmma::load_matrix_sync(bf[j], Bp + j * 16, BW3);
        }
#pragma unroll
        for (int i = 0; i < 2; i++)
#pragma unroll
            for (int j = 0; j < 4; j++) {
                wmma::mma_sync(acc[i][j], ah[i], bf[j], acc[i][j]);
                wmma::mma_sync(acc[i][j], al[i], bf[j], acc[i][j]);
            }
    };

#pragma unroll 1
    for (int hh = 0; hh < 2; hh++) {
#pragma unroll
        for (int i = 0; i < 2; i++)
#pragma unroll
            for (int j = 0; j < 4; j++) wmma::fill_fragment(acc[i][j], 0.f);

        stage3(0, 0, hh);
        CP_WAIT(0);
        __syncthreads();
        for (int ic = 0; ic < 32; ic++) {
            if (ic + 1 < 32) stage3((ic + 1) * KCH, (ic + 1) & 1, hh);
            compute3(ic * KCH, ic & 1, hh);
            if (ic + 1 < 32) CP_WAIT(0);
            __syncthreads();
        }

#pragma unroll
        for (int i = 0; i < 2; i++)
#pragma unroll
            for (int j = 0; j < 4; j++)
                wmma::store_matrix_sync(Es + (wid * 32 + i * 16) * EW3 + j * 16,
                                        acc[i][j], EW3, wmma::mem_row_major);
        __syncthreads();
        {
            const int m = tid >> 1, seg = tid & 1;
            const float bv = ka[OFF_BOUT + m] + ka[OFF_BSH + m];
            const float bg = ka[OFF_BOUT + 128 + m] + ka[OFF_BSH + 128 + m];
            const size_t base = ((size_t)b * 128 + m) * NPIX + n0 + hh * 64 + seg * 32;
            const float* ev = Es + m * EW3 + seg * 32;
            const float* eg = Es + (m + 128) * EW3 + seg * 32;
#pragma unroll
            for (int c = 0; c < 32; c += 4) {
                float4 x = *reinterpret_cast<const float4*>(&xold[base + c]);
                float4 o;
                { float v = ev[c+0] + bv, g = eg[c+0] + bg; o.x = x.x + leak * v / (1.f + __expf(-g)); }
                { float v = ev[c+1] + bv, g = eg[c+1] + bg; o.y = x.y + leak * v / (1.f + __expf(-g)); }
                { float v = ev[c+2] + bv, g = eg[c+2] + bg; o.z = x.z + leak * v / (1.f + __expf(-g)); }
                { float v = ev[c+3] + bv, g = eg[c+3] + bg; o.w = x.w + leak * v / (1.f + __expf(-g)); }
                *reinterpret_cast<float4*>(&xnew[base + c]) = o;
            }
        }
        __syncthreads();
    }
}

// ======================================================================
// wmma fp16 GEMM (conv tail only): 2-term, 3-stage / 1 sync, MBLKS=1
// ======================================================================
__global__ void __launch_bounds__(256, 2) gemm_conv(
    const __half* __restrict__ Wh, const __half* __restrict__ Wl,
    int Ktot, const __half* __restrict__ B1,
    const float* __restrict__ bias_dir,
    float* __restrict__ outf, __half* __restrict__ outh,
    const float* __restrict__ xold)
{
    constexpr int KCH = 32;
    constexpr int AW = 40;
    constexpr int BW = 136;
    constexpr int EW = 132;
    constexpr int BUFE = 2 * 128 * AW + KCH * BW;

    extern __shared__ __align__(16) char sm[];
    __half* smB = (__half*)sm;
    float* Es = (float*)sm;

    const int tid = threadIdx.x;
    const int b = blockIdx.y;
    const int n0 = blockIdx.x * 128;
    const int wid = tid >> 5;
    const int wm = wid >> 1, wn = wid & 1;

    const __half* WhB = Wh + (size_t)b * 128 * Ktot;
    const __half* WlB = Wl + (size_t)b * 128 * Ktot;
    const __half* Bb = B1 + (size_t)b * Ktot * NPIX;

    wmma::fragment<wmma::accumulator, 16, 16, 16, float> acc[2][4];
#pragma unroll
    for (int i = 0; i < 2; i++)
#pragma unroll
        for (int j = 0; j < 4; j++) wmma::fill_fragment(acc[i][j], 0.f);

    auto stage = [&](int kc, int s) {
        __half* Ahd = smB + (size_t)s * BUFE;
        __half* Ald = Ahd + 128 * AW;
        __half* Bfd = Ald + 128 * AW;
#pragma unroll
        for (int i = tid; i < 1024; i += 256) {
            int plane = (i >= 512);
            int rem = i - plane * 512;
            int m = rem >> 2, q = rem & 3;
            const __half* src = (plane ? WlB : WhB) + (size_t)m * Ktot + kc + q * 8;
            unsigned d = (unsigned)__cvta_generic_to_shared(
                (plane ? Ald : Ahd) + m * AW + q * 8);
            CP16(d, src);
        }
#pragma unroll
        for (int i = tid; i < 512; i += 256) {
            int k = i >> 4, c = (i & 15) * 8;
            const __half* src = Bb + (size_t)(kc + k) * NPIX + n0 + c;
            unsigned d = (unsigned)__cvta_generic_to_shared(Bfd + k * BW + c);
            CP16(d, src);
        }
        CP_COMMIT();
    };

    auto compute = [&](int s) {
        const __half* Ahd = smB + (size_t)s * BUFE;
        const __half* Ald = Ahd + 128 * AW;
        const __half* Bfd = Ald + 128 * AW;
#pragma unroll
        for (int kk = 0; kk < 2; kk++) {
            wmma::fragment<wmma::matrix_a, 16, 16, 16, __half, wmma::row_major> ah[2], al[2];
            wmma::fragment<wmma::matrix_b, 16, 16, 16, __half, wmma::row_major> bf[4];
#pragma unroll
            for (int i = 0; i < 2; i++) {
                wmma::load_matrix_sync(ah[i], Ahd + (wm * 32 + i * 16) * AW + kk * 16, AW);
                wmma::load_matrix_sync(al[i], Ald + (wm * 32 + i * 16) * AW + kk * 16, AW);
            }
#pragma unroll
            for (int j = 0; j < 4; j++)
                wmma::load_matrix_sync(bf[j], Bfd + kk * 16 * BW + wn * 64 + j * 16, BW);
#pragma unroll
            for (int i = 0; i < 2; i++)
#pragma unroll
                for (int j = 0; j < 4; j++) {
                    wmma::mma_sync(acc[i][j], ah[i], bf[j], acc[i][j]);
                    wmma::mma_sync(acc[i][j], al[i], bf[j], acc[i][j]);
                }
        }
    };

    const int nch = Ktot / KCH;
    stage(0, 0);
    stage(KCH, 1);
    CP_WAIT(1);
    __syncthreads();
    for (int ic = 0; ic < nch; ic++) {
        compute(ic % 3);
        if (ic + 2 < nch) {
            stage((ic + 2) * KCH, (ic + 2) % 3);
            CP_WAIT(1);
        } else {
            CP_WAIT(0);
        }
        __syncthreads();
    }

#pragma unroll
    for (int i = 0; i < 2; i++)
#pragma unroll
        for (int j = 0; j < 4; j++)
            wmma::store_matrix_sync(Es + (wm * 32 + i * 16) * EW + wn * 64 + j * 16,
                                    acc[i][j], EW, wmma::mem_row_major);
    __syncthreads();

    const int m = tid >> 1, seg = tid & 1;
    const float bias = bias_dir[m];
    const size_t base = ((size_t)b * 128 + m) * NPIX + n0 + seg * 64;
    const float* er = Es + m * EW + seg * 64;
    if (outh) {
#pragma unroll
        for (int c = 0; c < 64; c += 2) {
            __half2 o;
            o.x = __float2half_rn(fmaxf(er[c + 0] + bias, 0.f));
            o.y = __float2half_rn(fmaxf(er[c + 1] + bias, 0.f));
            *reinterpret_cast<__half2*>(&outh[base + c]) = o;
        }
    } else {
#pragma unroll
        for (int c = 0; c < 64; c += 4) {
            float4 o;
            o.x = er[c+0] + bias; o.y = er[c+1] + bias;
            o.z = er[c+2] + bias; o.w = er[c+3] + bias;
            float4 x = *reinterpret_cast<const float4*>(&xold[base + c]);
            o.x += x.x; o.y += x.y; o.z += x.z; o.w += x.w;
            *reinterpret_cast<float4*>(&outf[base + c]) = o;
        }
    }
}

// ======================================================================
// final 128->3 conv + clip
// ======================================================================
__global__ void __launch_bounds__(256) conv_img_kernel(
    const float* __restrict__ X, const float* __restrict__ W,
    const float* __restrict__ bias,
    float* __restrict__ out_img, float* __restrict__ out_raw)
{
    const int b = blockIdx.y, y0 = blockIdx.x * 4, tid = threadIdx.x;
    const int r = tid >> 6, x = tid & 63;
    __shared__ float sW[3 * 1152];
    __shared__ float sIn[6][66];
    for (int i = tid; i < 3 * 1152; i += 256) sW[i] = W[i];
    float acc[3] = {0.f, 0.f, 0.f};
    const float* Xb = X + (size_t)b * NF * NPIX;
    for (int ci = 0; ci < NF; ci++) {
        __syncthreads();
        for (int i = tid; i < 6 * 66; i += 256) {
            int ry = i / 66, cx = i - ry * 66;
            int gy = y0 - 1 + ry, gx = cx - 1;
            float v = 0.f;
            if ((unsigned)gy < 64u && (unsigned)gx < 64u)
                v = Xb[(size_t)ci * NPIX + gy * 64 + gx];
            sIn[ry][cx] = v;
        }
        __syncthreads();
        float in[9];
#pragma unroll
        for (int dy = 0; dy < 3; dy++)
#pragma unroll
            for (int dx = 0; dx < 3; dx++) in[dy * 3 + dx] = sIn[r + dy][x + dx];
#pragma unroll
        for (int o = 0; o < 3; o++)
#pragma unroll
            for (int j = 0; j < 9; j++)
                acc[o] = fmaf(in[j], sW[o * 1152 + ci * 9 + j], acc[o]);
    }
#pragma unroll
    for (int o = 0; o < 3; o++) {
        float v = acc[o] + bias[o];
        size_t idx = ((size_t)b * 3 + o) * NPIX + (size_t)(y0 + r) * 64 + x;
        out_raw[idx] = v;
        out_img[idx] = fminf(fmaxf(v, -1.f), 1.f);
    }
}

// ======================================================================
extern "C" void kernel_launch(void* const* d_in, const int* in_sizes, int n_in,
                              void* d_out, int out_size)
{
    const float* lat  = (const float*)d_in[0];
    const float* ca   = (const float*)d_in[1];
    const float* leak = (const float*)d_in[2];
    const float* hw   = (const float*)d_in[3];
    const float* hb   = (const float*)d_in[4];
    const float* rw1  = (const float*)d_in[5];
    const float* rb1  = (const float*)d_in[6];
    const float* rw2  = (const float*)d_in[7];
    const float* rb2  = (const float*)d_in[8];
    const float* iw   = (const float*)d_in[9];
    const float* ib   = (const float*)d_in[10];

    float* out = (float*)d_out;
    float* out_img = out;
    float* embs    = out + 98304;
    float* out_raw = out + 98304 + (size_t)17 * 4194304;

    float *kall, *c2;
    __half *pf, *colf;
    __half *w1h, *w1l, *w2h, *w2l, *w3h, *w3l, *r1h, *r1l, *r2h, *r2l;
    cudaGetSymbolAddress((void**)&kall, g_kall);
    cudaGetSymbolAddress((void**)&pf,  g_pf);
    cudaGetSymbolAddress((void**)&w1h, g_w1h); cudaGetSymbolAddress((void**)&w1l, g_w1l);
    cudaGetSymbolAddress((void**)&w2h, g_w2h); cudaGetSymbolAddress((void**)&w2l, g_w2l);
    cudaGetSymbolAddress((void**)&w3h, g_w3h); cudaGetSymbolAddress((void**)&w3l, g_w3l);
    cudaGetSymbolAddress((void**)&colf, g_colf);
    cudaGetSymbolAddress((void**)&r1h, g_rw1h); cudaGetSymbolAddress((void**)&r1l, g_rw1l);
    cudaGetSymbolAddress((void**)&r2h, g_rw2h); cudaGetSymbolAddress((void**)&r2l, g_rw2l);
    cudaGetSymbolAddress((void**)&c2, g_c2);

    const int SM1 = 87552;   // gemm_conv: 3 x (2*128*40 + 32*136) * 2B
    const int SMF = 104448;  // step_kernel: region A 69632 + H 34816
    cudaFuncSetAttribute(gemm_conv, cudaFuncAttributeMaxDynamicSharedMemorySize, SM1);
    cudaFuncSetAttribute(step_kernel, cudaFuncAttributeMaxDynamicSharedMemorySize, SMF);

    hyper_kernel<<<KT / 256, 256>>>(lat, hw, hb, kall);
    pack_rw_kernel<<<576, 256>>>(rw1, r1h, r1l);
    pack_rw_kernel<<<576, 256>>>(rw2, r2h, r2l);
    cudaMemcpyAsync(embs, ca, (size_t)4194304 * sizeof(float), cudaMemcpyDeviceToDevice);

    for (int t = 0; t < NCALLS; t++) {
        float* x  = embs + (size_t)t * 4194304;
        float* xn = x + 4194304;
        build_p_kernel<<<dim3(NF, NB), 256>>>(x, pf);
        step_kernel<<<dim3(32, NB), 256, SMF>>>(
            w1h, w1l, w2h, w2l, w3h, w3l, pf, kall, x, xn, leak);
    }

    float* xf = embs + (size_t)NCALLS * 4194304;
    im2col_f32_kernel<<<147456, 256>>>(xf, colf);
    gemm_conv<<<dim3(32, NB), 256, SM1>>>(r1h, r1l, 1152, colf, rb1, nullptr, pf, nullptr);
    im2col_h_kernel<<<147456, 256>>>(pf, colf);
    gemm_conv<<<dim3(32, NB), 256, SM1>>>(r2h, r2l, 1152, colf, rb2, c2, nullptr, xf);
    conv_img_kernel<<<dim3(16, NB), 256>>>(c2, iw, ib, out_img, out_raw);
}

// round 14
// speedup vs baseline: 1.0111x; 1.0111x over previous
#include <cuda_runtime.h>
#include <cuda_fp16.h>
#include <mma.h>
#include <math.h>

using namespace nvcuda;

#define NB 8
#define NF 128
#define LATD 256
#define NPIX 4096
#define NCALLS 16
#define FIN 384
#define KT 197376

#define OFF_WIN  0
#define OFF_BIN  49152
#define OFF_WMID 49280
#define OFF_BMID 65664
#define OFF_WOUT 65792
#define OFF_BOUT 98560
#define OFF_WSH  98816
#define OFF_BSH  197120

#define COLSZ 4718592   // 1152 * 4096 (NOT a power of 2 — true division!)

// -------- scratch --------
__device__ __align__(16) float g_kall[NB * KT];
__device__ __align__(16) __half g_pf [NB * FIN * NPIX];
__device__ __align__(16) __half g_h2f[NB * NF * NPIX];
__device__ __align__(16) __half g_w1h[NB * 128 * 384], g_w1l[NB * 128 * 384];
__device__ __align__(16) __half g_w2h[NB * 128 * 128], g_w2l[NB * 128 * 128];
__device__ __align__(16) __half g_w3h[NB * 256 * 512], g_w3l[NB * 256 * 512];
__device__ __align__(16) __half g_colf[NB * 1152 * NPIX];
__device__ __align__(16) __half g_rw1h[NB * 147456], g_rw1l[NB * 147456];
__device__ __align__(16) __half g_rw2h[NB * 147456], g_rw2l[NB * 147456];
__device__ __align__(16) float g_c2[NB * NF * NPIX];

#define CP16(dst, src) \
    asm volatile("cp.async.cg.shared.global [%0], [%1], 16;\n" :: "r"(dst), "l"(src))
#define CP_COMMIT() asm volatile("cp.async.commit_group;\n" ::: "memory")
#define CP_WAIT(n)  asm volatile("cp.async.wait_group %0;\n" :: "n"(n) : "memory")

__device__ __forceinline__ void splitA(float v, __half& h, __half& l) {
    h = __float2half_rn(v);
    l = __float2half_rn(v - __half2float(h));
}

// ======================================================================
// hyper + pack fused
// ======================================================================
__global__ void __launch_bounds__(256) hyper_kernel(
    const float* __restrict__ lat, const float* __restrict__ hw,
    const float* __restrict__ hb, float* __restrict__ kall)
{
    __shared__ float ls[NB * LATD];
    const int tid = threadIdx.x;
    for (int i = tid; i < NB * LATD; i += 256) ls[i] = lat[i];
    __syncthreads();
    const int n = blockIdx.x * 256 + tid;
    float acc[NB];
#pragma unroll
    for (int b = 0; b < NB; b++) acc[b] = 0.f;
    for (int k = 0; k < LATD; k++) {
        float w = hw[(size_t)k * KT + n];
#pragma unroll
        for (int b = 0; b < NB; b++) acc[b] = fmaf(ls[b * LATD + k], w, acc[b]);
    }
    const float bias = hb[n];

    float s = 1.f;
    int kind;
    size_t widx = 0;
    if (n < OFF_BIN)       { s = 0.05103103630798288f; kind = 0; widx = n; }
    else if (n < OFF_WMID) { kind = 3; }
    else if (n < OFF_BMID) { s = 0.08838834764831845f; kind = 1; widx = n - OFF_WMID; }
    else if (n < OFF_WOUT) { kind = 3; }
    else if (n < OFF_BOUT) {
        s = 0.08838834764831845f; kind = 2;
        int i = n - OFF_WOUT;
        widx = (size_t)(i >> 7) * 512 + (i & 127);
    } else if (n < OFF_WSH) { kind = 3; }
    else if (n < OFF_BSH) {
        s = 0.05103103630798288f; kind = 2;
        int i = n - OFF_WSH;
        widx = (size_t)(i / 384) * 512 + 128 + (i % 384);
    } else kind = 3;

#pragma unroll
    for (int b = 0; b < NB; b++) {
        float v = (acc[b] + bias) * s;
        if (kind == 3) {
            kall[(size_t)b * KT + n] = v;
        } else {
            __half h, l;
            splitA(v, h, l);
            if (kind == 0)      { g_w1h[(size_t)b * 49152 + widx] = h;  g_w1l[(size_t)b * 49152 + widx] = l; }
            else if (kind == 1) { g_w2h[(size_t)b * 16384 + widx] = h;  g_w2l[(size_t)b * 16384 + widx] = l; }
            else                { g_w3h[(size_t)b * 131072 + widx] = h; g_w3l[(size_t)b * 131072 + widx] = l; }
        }
    }
}

// ======================================================================
// pack res-conv weights
// ======================================================================
__global__ void __launch_bounds__(256) pack_rw_kernel(
    const float* __restrict__ w, __half* __restrict__ dh, __half* __restrict__ dl)
{
    const int idx = blockIdx.x * 256 + threadIdx.x;
    const int o = idx / 1152, r = idx - o * 1152;
    const int t = r >> 7, c = r & 127;
    float v = w[o * 1152 + c * 9 + t];
    __half h, l;
    splitA(v, h, l);
#pragma unroll
    for (int b = 0; b < NB; b++) {
        dh[(size_t)b * 147456 + idx] = h;
        dl[(size_t)b * 147456 + idx] = l;
    }
}

// ======================================================================
// im2col
// ======================================================================
__global__ void __launch_bounds__(256) im2col_f32_kernel(
    const float* __restrict__ src, __half* __restrict__ d)
{
    const size_t idx = (size_t)blockIdx.x * 256 + threadIdx.x;
    const int b = (int)(idx / COLSZ);
    const size_t r = idx - (size_t)b * COLSZ;
    const int k = (int)(r >> 12), px = (int)(r & 4095);
    const int tap = k >> 7, ch = k & 127;
    const int dy = tap / 3 - 1, dx = tap % 3 - 1;
    const int y = (px >> 6) + dy, x = (px & 63) + dx;
    float v = 0.f;
    if ((unsigned)y < 64u && (unsigned)x < 64u)
        v = src[(((size_t)b * 128 + ch) << 12) + y * 64 + x];
    d[idx] = __float2half_rn(v);
}

__global__ void __launch_bounds__(256) im2col_h_kernel(
    const __half* __restrict__ src, __half* __restrict__ d)
{
    const size_t idx = (size_t)blockIdx.x * 256 + threadIdx.x;
    const int b = (int)(idx / COLSZ);
    const size_t r = idx - (size_t)b * COLSZ;
    const int k = (int)(r >> 12), px = (int)(r & 4095);
    const int tap = k >> 7, ch = k & 127;
    const int dy = tap / 3 - 1, dx = tap % 3 - 1;
    const int y = (px >> 6) + dy, x = (px & 63) + dx;
    __half v = __float2half_rn(0.f);
    if ((unsigned)y < 64u && (unsigned)x < 64u)
        v = src[(((size_t)b * 128 + ch) << 12) + y * 64 + x];
    d[idx] = v;
}

// ======================================================================
// build_p -> single fp16 plane; paired half2 stores (even lanes)
// ======================================================================
__global__ void __launch_bounds__(256) build_p_kernel(
    const float* __restrict__ X, __half* __restrict__ P)
{
    const int c = blockIdx.x, b = blockIdx.y, tid = threadIdx.x;
    __shared__ float sp[68 * 68];
    __shared__ float red[8][6];
    __shared__ float stats[6];
    for (int i = tid; i < 68 * 68; i += 256) sp[i] = 0.f;
    __syncthreads();
    const float* Xp = X + ((size_t)b * NF + c) * NPIX;
    for (int i = tid; i < NPIX; i += 256) {
        int y = i >> 6, x = i & 63;
        sp[(y + 2) * 68 + (x + 2)] = Xp[i];
    }
    __syncthreads();
    const float C = 0.70710678118654752f;
    float vx[16], vsx[16], vsy[16];
    float s0 = 0.f, q0 = 0.f, s1 = 0.f, q1 = 0.f, s2 = 0.f, q2 = 0.f;
#pragma unroll
    for (int it = 0; it < 16; it++) {
        int pix = tid + it * 256;
        int y = pix >> 6, x = pix & 63;
        const float* B = &sp[y * 68 + x];
        float xv = B[2*68+2];
        float sx = C*(B[1*68+4]-B[1*68+0]) + 0.5f*(B[1*68+3]-B[1*68+1])
                 + (B[2*68+4]-B[2*68+0]) + C*(B[2*68+3]-B[2*68+1])
                 + C*(B[3*68+4]-B[3*68+0]) + 0.5f*(B[3*68+3]-B[3*68+1]);
        float sy = C*(B[4*68+1]-B[0*68+1]) + (B[4*68+2]-B[0*68+2])
                 + C*(B[4*68+3]-B[0*68+3])
                 + 0.5f*(B[3*68+1]-B[1*68+1]) + C*(B[3*68+2]-B[1*68+2])
                 + 0.5f*(B[3*68+3]-B[1*68+3]);
        vx[it] = xv; vsx[it] = sx; vsy[it] = sy;
        s0 += xv; q0 = fmaf(xv, xv, q0);
        s1 += sx; q1 = fmaf(sx, sx, q1);
        s2 += sy; q2 = fmaf(sy, sy, q2);
    }
#pragma unroll
    for (int off = 16; off; off >>= 1) {
        s0 += __shfl_down_sync(~0u, s0, off); q0 += __shfl_down_sync(~0u, q0, off);
        s1 += __shfl_down_sync(~0u, s1, off); q1 += __shfl_down_sync(~0u, q1, off);
        s2 += __shfl_down_sync(~0u, s2, off); q2 += __shfl_down_sync(~0u, q2, off);
    }
    if ((tid & 31) == 0) {
        int w = tid >> 5;
        red[w][0]=s0; red[w][1]=q0; red[w][2]=s1; red[w][3]=q1; red[w][4]=s2; red[w][5]=q2;
    }
    __syncthreads();
    if (tid == 0) {
        float S[6] = {0,0,0,0,0,0};
        for (int w = 0; w < 8; w++) for (int j = 0; j < 6; j++) S[j] += red[w][j];
        const float invN = 1.f / 4096.f;
#pragma unroll
        for (int t3 = 0; t3 < 3; t3++) {
            float mu = S[2*t3] * invN;
            float var = fmaxf(S[2*t3+1] * invN - mu*mu, 0.f);
            stats[2*t3] = mu; stats[2*t3+1] = rsqrtf(var + 1e-5f);
        }
    }
    __syncthreads();
    const float mu0 = stats[0], in0 = stats[1], mu1 = stats[2], in1 = stats[3],
                mu2 = stats[4], in2 = stats[5];
    const size_t p0 = ((size_t)b * FIN + c) * NPIX;
    const bool even = !(tid & 1);
#pragma unroll
    for (int it = 0; it < 16; it++) {
        int pix = tid + it * 256;
        float v0 = (vx[it]  - mu0) * in0;
        float v1 = (vsx[it] - mu1) * in1;
        float v2 = (vsy[it] - mu2) * in2;
        float n0 = __shfl_down_sync(~0u, v0, 1);
        float n1 = __shfl_down_sync(~0u, v1, 1);
        float n2 = __shfl_down_sync(~0u, v2, 1);
        if (even) {
            __half2 o0; o0.x = __float2half_rn(v0); o0.y = __float2half_rn(n0);
            __half2 o1; o1.x = __float2half_rn(v1); o1.y = __float2half_rn(n1);
            __half2 o2; o2.x = __float2half_rn(v2); o2.y = __float2half_rn(n2);
            *reinterpret_cast<__half2*>(&P[p0 + pix]) = o0;
            *reinterpret_cast<__half2*>(&P[p0 + (size_t)NF*NPIX + pix]) = o1;
            *reinterpret_cast<__half2*>(&P[p0 + (size_t)2*NF*NPIX + pix]) = o2;
        }
    }
}

// ======================================================================
// FUSED g1+g2: h2 = relu(W2 @ relu(W1 @ p + b1) + b2), h1 lives in smem.
// ======================================================================
__global__ void __launch_bounds__(256, 2) mlp12_kernel(
    const __half* __restrict__ W1h, const __half* __restrict__ W1l,
    const __half* __restrict__ W2h, const __half* __restrict__ W2l,
    const __half* __restrict__ P, const float* __restrict__ kall,
    __half* __restrict__ H2out)
{
    constexpr int KCH = 16;
    constexpr int AW = 24;
    constexpr int BW = 136;
    constexpr int EW = 132;
    constexpr int A_ELEMS = 128 * AW;
    constexpr int BUF1 = 2 * A_ELEMS + KCH * BW;
    constexpr int BUF2 = 2 * A_ELEMS;

    extern __shared__ __align__(16) char sm[];
    __half* smH = (__half*)sm;
    float* Es = (float*)sm;
    __half* H = (__half*)(sm + 69632);

    const int tid = threadIdx.x;
    const int b = blockIdx.y;
    const int n0 = blockIdx.x * 128;
    const int wid = tid >> 5;
    const int wm = wid >> 1, wn = wid & 1;

    const __half* W1hB = W1h + (size_t)b * 49152;
    const __half* W1lB = W1l + (size_t)b * 49152;
    const __half* W2hB = W2h + (size_t)b * 16384;
    const __half* W2lB = W2l + (size_t)b * 16384;
    const __half* Pb = P + (size_t)b * FIN * NPIX;

    wmma::fragment<wmma::accumulator, 16, 16, 16, float> acc[2][4];
#pragma unroll
    for (int i = 0; i < 2; i++)
#pragma unroll
        for (int j = 0; j < 4; j++) wmma::fill_fragment(acc[i][j], 0.f);

    auto stage1 = [&](int kc, int s) {
        __half* Ah = smH + (size_t)s * BUF1;
        __half* Al = Ah + A_ELEMS;
        __half* Bf = Al + A_ELEMS;
#pragma unroll
        for (int i = tid; i < 512; i += 256) {
            int plane = (i >= 256);
            int rem = i - plane * 256;
            int m = rem >> 1, q = rem & 1;
            const __half* src = (plane ? W1lB : W1hB) + (size_t)m * 384 + kc + q * 8;
            unsigned d = (unsigned)__cvta_generic_to_shared(
                (plane ? Al : Ah) + m * AW + q * 8);
            CP16(d, src);
        }
        {
            int k = tid >> 4, c = (tid & 15) * 8;
            const __half* src = Pb + (size_t)(kc + k) * NPIX + n0 + c;
            unsigned d = (unsigned)__cvta_generic_to_shared(Bf + k * BW + c);
            CP16(d, src);
        }
        CP_COMMIT();
    };
    auto compute1 = [&](int s) {
        const __half* Ah = smH + (size_t)s * BUF1;
        const __half* Al = Ah + A_ELEMS;
        const __half* Bf = Al + A_ELEMS;
        wmma::fragment<wmma::matrix_a, 16, 16, 16, __half, wmma::row_major> ah[2], al[2];
        wmma::fragment<wmma::matrix_b, 16, 16, 16, __half, wmma::row_major> bf[4];
#pragma unroll
        for (int i = 0; i < 2; i++) {
            wmma::load_matrix_sync(ah[i], Ah + (wm * 32 + i * 16) * AW, AW);
            wmma::load_matrix_sync(al[i], Al + (wm * 32 + i * 16) * AW, AW);
        }
#pragma unroll
        for (int j = 0; j < 4; j++)
            wmma::load_matrix_sync(bf[j], Bf + wn * 64 + j * 16, BW);
#pragma unroll
        for (int i = 0; i < 2; i++)
#pragma unroll
            for (int j = 0; j < 4; j++) {
                wmma::mma_sync(acc[i][j], ah[i], bf[j], acc[i][j]);
                wmma::mma_sync(acc[i][j], al[i], bf[j], acc[i][j]);
            }
    };

    {
        const int nch = 24;
        stage1(0, 0);
        stage1(KCH, 1);
        CP_WAIT(1);
        __syncthreads();
        for (int ic = 0; ic < nch; ic++) {
            compute1(ic % 3);
            if (ic + 2 < nch) {
                stage1((ic + 2) * KCH, (ic + 2) % 3);
                CP_WAIT(1);
            } else {
                CP_WAIT(0);
            }
            __syncthreads();
        }
    }
#pragma unroll
    for (int i = 0; i < 2; i++)
#pragma unroll
        for (int j = 0; j < 4; j++)
            wmma::store_matrix_sync(Es + (wm * 32 + i * 16) * EW + wn * 64 + j * 16,
                                    acc[i][j], EW, wmma::mem_row_major);
    __syncthreads();
    {
        const int m = tid >> 1, seg = tid & 1;
        const float bias1 = kall[(size_t)b * KT + OFF_BIN + m];
        const float* er = Es + m * EW + seg * 64;
        __half* hr = H + m * BW + seg * 64;
#pragma unroll
        for (int c = 0; c < 64; c += 2) {
            __half2 o;
            o.x = __float2half_rn(fmaxf(er[c + 0] + bias1, 0.f));
            o.y = __float2half_rn(fmaxf(er[c + 1] + bias1, 0.f));
            *reinterpret_cast<__half2*>(&hr[c]) = o;
        }
    }
    __syncthreads();

#pragma unroll
    for (int i = 0; i < 2; i++)
#pragma unroll
        for (int j = 0; j < 4; j++) wmma::fill_fragment(acc[i][j], 0.f);

    auto stage2 = [&](int kc, int s) {
        __half* Ah = smH + (size_t)s * BUF2;
        __half* Al = Ah + A_ELEMS;
#pragma unroll
        for (int i = tid; i < 512; i += 256) {
            int plane = (i >= 256);
            int rem = i - plane * 256;
            int m = rem >> 1, q = rem & 1;
            const __half* src = (plane ? W2lB : W2hB) + (size_t)m * 128 + kc + q * 8;
            unsigned d = (unsigned)__cvta_generic_to_shared(
                (plane ? Al : Ah) + m * AW + q * 8);
            CP16(d, src);
        }
        CP_COMMIT();
    };
    auto compute2 = [&](int kc, int s) {
        const __half* Ah = smH + (size_t)s * BUF2;
        const __half* Al = Ah + A_ELEMS;
        wmma::fragment<wmma::matrix_a, 16, 16, 16, __half, wmma::row_major> ah[2], al[2];
        wmma::fragment<wmma::matrix_b, 16, 16, 16, __half, wmma::row_major> bf[4];
#pragma unroll
        for (int i = 0; i < 2; i++) {
            wmma::load_matrix_sync(ah[i], Ah + (wm * 32 + i * 16) * AW, AW);
            wmma::load_matrix_sync(al[i], Al + (wm * 32 + i * 16) * AW, AW);
        }
#pragma unroll
        for (int j = 0; j < 4; j++)
            wmma::load_matrix_sync(bf[j], H + kc * BW + wn * 64 + j * 16, BW);
#pragma unroll
        for (int i = 0; i < 2; i++)
#pragma unroll
            for (int j = 0; j < 4; j++) {
                wmma::mma_sync(acc[i][j], ah[i], bf[j], acc[i][j]);
                wmma::mma_sync(acc[i][j], al[i], bf[j], acc[i][j]);
            }
    };

    {
        const int nch = 8;
        stage2(0, 0);
        stage2(KCH, 1);
        CP_WAIT(1);
        __syncthreads();
        for (int ic = 0; ic < nch; ic++) {
            compute2(ic * KCH, ic % 3);
            if (ic + 2 < nch) {
                stage2((ic + 2) * KCH, (ic + 2) % 3);
                CP_WAIT(1);
            } else {
                CP_WAIT(0);
            }
            __syncthreads();
        }
    }
#pragma unroll
    for (int i = 0; i < 2; i++)
#pragma unroll
        for (int j = 0; j < 4; j++)
            wmma::store_matrix_sync(Es + (wm * 32 + i * 16) * EW + wn * 64 + j * 16,
                                    acc[i][j], EW, wmma::mem_row_major);
    __syncthreads();
    {
        const int m = tid >> 1, seg = tid & 1;
        const float bias2 = kall[(size_t)b * KT + OFF_BMID + m];
        const size_t base = ((size_t)b * 128 + m) * NPIX + n0 + seg * 64;
        const float* er = Es + m * EW + seg * 64;
#pragma unroll
        for (int c = 0; c < 64; c += 2) {
            __half2 o;
            o.x = __float2half_rn(fmaxf(er[c + 0] + bias2, 0.f));
            o.y = __float2half_rn(fmaxf(er[c + 1] + bias2, 0.f));
            *reinterpret_cast<__half2*>(&H2out[base + c]) = o;
        }
    }
}

// ======================================================================
// wmma fp16 GEMM: 2-term, 3-stage / 1 sync.
// MBLKS=1 (KCH=32): conv tail; MBLKS=2 (KCH=16): g3 gated update
// ======================================================================
template<int MBLKS>
__global__ void __launch_bounds__(256, 2) gemm_wmma(
    const __half* __restrict__ Wh, const __half* __restrict__ Wl,
    int Ktot,
    const __half* __restrict__ B1, int K1, const __half* __restrict__ B2,
    const float* __restrict__ kall, int boff1, int boff2,
    const float* __restrict__ bias_dir,
    float* __restrict__ outf, __half* __restrict__ outh,
    const float* __restrict__ xold, const float* __restrict__ leakp)
{
    constexpr int MT = MBLKS * 128;
    constexpr int NT = 128 / MBLKS;
    constexpr int KCH = (MBLKS == 1) ? 32 : 16;
    constexpr int KK = KCH / 16;
    constexpr int AP = KCH / 8;
    constexpr int AW = KCH + 8;
    constexpr int BW = (MBLKS == 1) ? 136 : 72;
    constexpr int EW = NT + 4;
    constexpr int BUFE = 2 * MT * AW + KCH * BW;

    extern __shared__ __align__(16) char sm[];
    __half* smB = (__half*)sm;
    float* Es = (float*)sm;

    const int tid = threadIdx.x;
    const int b = blockIdx.y;
    const int n0 = blockIdx.x * NT;
    const int wid = tid >> 5;
    const int wm = (MBLKS == 1) ? (wid >> 1) : wid;
    const int wn = (MBLKS == 1) ? (wid & 1) : 0;

    const __half* WhB = Wh + (size_t)b * MT * Ktot;
    const __half* WlB = Wl + (size_t)b * MT * Ktot;

    wmma::fragment<wmma::accumulator, 16, 16, 16, float> acc[2][4];
#pragma unroll
    for (int i = 0; i < 2; i++)
#pragma unroll
        for (int j = 0; j < 4; j++) wmma::fill_fragment(acc[i][j], 0.f);

    auto stage = [&](int kc, int s) {
        __half* Ahd = smB + (size_t)s * BUFE;
        __half* Ald = Ahd + MT * AW;
        __half* Bfd = Ald + MT * AW;
#pragma unroll
        for (int i = tid; i < MT * AP * 2; i += 256) {
            int plane = (i >= MT * AP);
            int rem = i - plane * MT * AP;
            int m = rem / AP, q = rem - m * AP;
            const __half* src = (plane ? WlB : WhB) + (size_t)m * Ktot + kc + q * 8;
            unsigned d = (unsigned)__cvta_generic_to_shared(
                (plane ? Ald : Ahd) + m * AW + q * 8);
            CP16(d, src);
        }
        const __half* sf; int ch0;
        if (kc < K1) { sf = B1 + (size_t)b * K1 * NPIX; ch0 = kc; }
        else { sf = B2 + (size_t)b * (Ktot - K1) * NPIX; ch0 = kc - K1; }
        constexpr int NC8 = NT / 8;
#pragma unroll
        for (int i = tid; i < KCH * NC8; i += 256) {
            int k = i / NC8, c = (i - k * NC8) * 8;
            const __half* src = sf + (size_t)(ch0 + k) * NPIX + n0 + c;
            unsigned d = (unsigned)__cvta_generic_to_shared(Bfd + k * BW + c);
            CP16(d, src);
        }
        CP_COMMIT();
    };

    auto compute = [&](int s) {
        const __half* Ahd = smB + (size_t)s * BUFE;
        const __half* Ald = Ahd + MT * AW;
        const __half* Bfd = Ald + MT * AW;
#pragma unroll
        for (int kk = 0; kk < KK; kk++) {
            wmma::fragment<wmma::matrix_a, 16, 16, 16, __half, wmma::row_major> ah[2], al[2];
            wmma::fragment<wmma::matrix_b, 16, 16, 16, __half, wmma::row_major> bf[4];
#pragma unroll
            for (int i = 0; i < 2; i++) {
                wmma::load_matrix_sync(ah[i], Ahd + (wm * 32 + i * 16) * AW + kk * 16, AW);
                wmma::load_matrix_sync(al[i], Ald + (wm * 32 + i * 16) * AW + kk * 16, AW);
            }
#pragma unroll
            for (int j = 0; j < 4; j++)
                wmma::load_matrix_sync(bf[j], Bfd + kk * 16 * BW + wn * 64 + j * 16, BW);
#pragma unroll
            for (int i = 0; i < 2; i++)
#pragma unroll
                for (int j = 0; j < 4; j++) {
                    wmma::mma_sync(acc[i][j], ah[i], bf[j], acc[i][j]);
                    wmma::mma_sync(acc[i][j], al[i], bf[j], acc[i][j]);
                }
        }
    };

    const int nch = Ktot / KCH;
    stage(0, 0);
    stage(KCH, 1);
    CP_WAIT(1);
    __syncthreads();
    for (int ic = 0; ic < nch; ic++) {
        compute(ic % 3);
        if (ic + 2 < nch) {
            stage((ic + 2) * KCH, (ic + 2) % 3);
            CP_WAIT(1);
        } else {
            CP_WAIT(0);
        }
        __syncthreads();
    }

#pragma unroll
    for (int i = 0; i < 2; i++)
#pragma unroll
        for (int j = 0; j < 4; j++)
            wmma::store_matrix_sync(Es + (wm * 32 + i * 16) * EW + wn * 64 + j * 16,
                                    acc[i][j], EW, wmma::mem_row_major);
    __syncthreads();

    const int m = tid >> 1, seg = tid & 1;
    if (MBLKS == 1) {
        const float bias = kall ? kall[(size_t)b * KT + boff1 + m] : bias_dir[m];
        const size_t base = ((size_t)b * 128 + m) * NPIX + n0 + seg * 64;
        const float* er = Es + m * EW + seg * 64;
        if (outh) {
#pragma unroll
            for (int c = 0; c < 64; c += 2) {
                __half2 o;
                o.x = __float2half_rn(fmaxf(er[c + 0] + bias, 0.f));
                o.y = __float2half_rn(fmaxf(er[c + 1] + bias, 0.f));
                *reinterpret_cast<__half2*>(&outh[base + c]) = o;
            }
        } else {
#pragma unroll
            for (int c = 0; c < 64; c += 4) {
                float4 o;
                o.x = er[c+0] + bias; o.y = er[c+1] + bias;
                o.z = er[c+2] + bias; o.w = er[c+3] + bias;
                if (xold) {
                    float4 x = *reinterpret_cast<const float4*>(&xold[base + c]);
                    o.x += x.x; o.y += x.y; o.z += x.z; o.w += x.w;
                }
                *reinterpret_cast<float4*>(&outf[base + c]) = o;
            }
        }
    } else {
        const float leak = fminf(fmaxf(leakp[0], 0.001f), 1000.f);
        const float* ka = kall + (size_t)b * KT;
        const float bv = ka[boff1 + m] + ka[boff2 + m];
        const float bg = ka[boff1 + 128 + m] + ka[boff2 + 128 + m];
        const size_t base = ((size_t)b * 128 + m) * NPIX + n0 + seg * 32;
        const float* ev = Es + m * EW + seg * 32;
        const float* eg = Es + (m + 128) * EW + seg * 32;
#pragma unroll
        for (int c = 0; c < 32; c += 4) {
            float4 x = *reinterpret_cast<const float4*>(&xold[base + c]);
            float4 o;
            { float v = ev[c+0] + bv, g = eg[c+0] + bg; o.x = x.x + leak * v / (1.f + __expf(-g)); }
            { float v = ev[c+1] + bv, g = eg[c+1] + bg; o.y = x.y + leak * v / (1.f + __expf(-g)); }
            { float v = ev[c+2] + bv, g = eg[c+2] + bg; o.z = x.z + leak * v / (1.f + __expf(-g)); }
            { float v = ev[c+3] + bv, g = eg[c+3] + bg; o.w = x.w + leak * v / (1.f + __expf(-g)); }
            *reinterpret_cast<float4*>(&outf[base + c]) = o;
        }
    }
}

// ======================================================================
// final 128->3 conv + clip
// ======================================================================
__global__ void __launch_bounds__(256) conv_img_kernel(
    const float* __restrict__ X, const float* __restrict__ W,
    const float* __restrict__ bias,
    float* __restrict__ out_img, float* __restrict__ out_raw)
{
    const int b = blockIdx.y, y0 = blockIdx.x * 4, tid = threadIdx.x;
    const int r = tid >> 6, x = tid & 63;
    __shared__ float sW[3 * 1152];
    __shared__ float sIn[6][66];
    for (int i = tid; i < 3 * 1152; i += 256) sW[i] = W[i];
    float acc[3] = {0.f, 0.f, 0.f};
    const float* Xb = X + (size_t)b * NF * NPIX;
    for (int ci = 0; ci < NF; ci++) {
        __syncthreads();
        for (int i = tid; i < 6 * 66; i += 256) {
            int ry = i / 66, cx = i - ry * 66;
            int gy = y0 - 1 + ry, gx = cx - 1;
            float v = 0.f;
            if ((unsigned)gy < 64u && (unsigned)gx < 64u)
                v = Xb[(size_t)ci * NPIX + gy * 64 + gx];
            sIn[ry][cx] = v;
        }
        __syncthreads();
        float in[9];
#pragma unroll
        for (int dy = 0; dy < 3; dy++)
#pragma unroll
            for (int dx = 0; dx < 3; dx++) in[dy * 3 + dx] = sIn[r + dy][x + dx];
#pragma unroll
        for (int o = 0; o < 3; o++)
#pragma unroll
            for (int j = 0; j < 9; j++)
                acc[o] = fmaf(in[j], sW[o * 1152 + ci * 9 + j], acc[o]);
    }
#pragma unroll
    for (int o = 0; o < 3; o++) {
        float v = acc[o] + bias[o];
        size_t idx = ((size_t)b * 3 + o) * NPIX + (size_t)(y0 + r) * 64 + x;
        out_raw[idx] = v;
        out_img[idx] = fminf(fmaxf(v, -1.f), 1.f);
    }
}

// ======================================================================
extern "C" void kernel_launch(void* const* d_in, const int* in_sizes, int n_in,
                              void* d_out, int out_size)
{
    const float* lat  = (const float*)d_in[0];
    const float* ca   = (const float*)d_in[1];
    const float* leak = (const float*)d_in[2];
    const float* hw   = (const float*)d_in[3];
    const float* hb   = (const float*)d_in[4];
    const float* rw1  = (const float*)d_in[5];
    const float* rb1  = (const float*)d_in[6];
    const float* rw2  = (const float*)d_in[7];
    const float* rb2  = (const float*)d_in[8];
    const float* iw   = (const float*)d_in[9];
    const float* ib   = (const float*)d_in[10];

    float* out = (float*)d_out;
    float* out_img = out;
    float* embs    = out + 98304;
    float* out_raw = out + 98304 + (size_t)17 * 4194304;

    float *kall, *c2;
    __half *pf, *h2f, *colf;
    __half *w1h, *w1l, *w2h, *w2l, *w3h, *w3l, *r1h, *r1l, *r2h, *r2l;
    cudaGetSymbolAddress((void**)&kall, g_kall);
    cudaGetSymbolAddress((void**)&pf,  g_pf);
    cudaGetSymbolAddress((void**)&h2f, g_h2f);
    cudaGetSymbolAddress((void**)&w1h, g_w1h); cudaGetSymbolAddress((void**)&w1l, g_w1l);
    cudaGetSymbolAddress((void**)&w2h, g_w2h); cudaGetSymbolAddress((void**)&w2l, g_w2l);
    cudaGetSymbolAddress((void**)&w3h, g_w3h); cudaGetSymbolAddress((void**)&w3l, g_w3l);
    cudaGetSymbolAddress((void**)&colf, g_colf);
    cudaGetSymbolAddress((void**)&r1h, g_rw1h); cudaGetSymbolAddress((void**)&r1l, g_rw1l);
    cudaGetSymbolAddress((void**)&r2h, g_rw2h); cudaGetSymbolAddress((void**)&r2l, g_rw2l);
    cudaGetSymbolAddress((void**)&c2, g_c2);

    const int SM1 = 87552;   // gemm<1>
    const int SM2 = 80640;   // gemm<2>
    const int SMF = 104448;  // mlp12
    cudaFuncSetAttribute(gemm_wmma<1>, cudaFuncAttributeMaxDynamicSharedMemorySize, SM1);
    cudaFuncSetAttribute(gemm_wmma<2>, cudaFuncAttributeMaxDynamicSharedMemorySize, SM2);
    cudaFuncSetAttribute(mlp12_kernel, cudaFuncAttributeMaxDynamicSharedMemorySize, SMF);

    hyper_kernel<<<KT / 256, 256>>>(lat, hw, hb, kall);
    pack_rw_kernel<<<576, 256>>>(rw1, r1h, r1l);
    pack_rw_kernel<<<576, 256>>>(rw2, r2h, r2l);
    cudaMemcpyAsync(embs, ca, (size_t)4194304 * sizeof(float), cudaMemcpyDeviceToDevice);

    for (int t = 0; t < NCALLS; t++) {
        float* x  = embs + (size_t)t * 4194304;
        float* xn = x + 4194304;

        build_p_kernel<<<dim3(NF, NB), 256>>>(x, pf);
        mlp12_kernel<<<dim3(32, NB), 256, SMF>>>(w1h, w1l, w2h, w2l, pf, kall, h2f);
        gemm_wmma<2><<<dim3(64, NB), 256, SM2>>>(
            w3h, w3l, 512, h2f, 128, pf,
            kall, OFF_BOUT, OFF_BSH, nullptr, xn, nullptr, x, leak);
    }

    float* xf = embs + (size_t)NCALLS * 4194304;
    im2col_f32_kernel<<<147456, 256>>>(xf, colf);
    gemm_wmma<1><<<dim3(32, NB), 256, SM1>>>(
        r1h, r1l, 1152, colf, 1152, nullptr,
        nullptr, 0, 0, rb1, nullptr, pf, nullptr, nullptr);
    im2col_h_kernel<<<147456, 256>>>(pf, colf);
    gemm_wmma<1><<<dim3(32, NB), 256, SM1>>>(
        r2h, r2l, 1152, colf, 1152, nullptr,
        nullptr, 0, 0, rb2, c2, nullptr, xf, nullptr);
    conv_img_kernel<<<dim3(16, NB), 256>>>(c2, iw, ib, out_img, out_raw);
}

// round 15
// speedup vs baseline: 1.3647x; 1.3498x over previous
#include <cuda_runtime.h>
#include <cuda_fp16.h>
#include <mma.h>
#include <math.h>

using namespace nvcuda;

#define NB 8
#define NF 128
#define LATD 256
#define NPIX 4096
#define NCALLS 16
#define FIN 384
#define KT 197376

#define OFF_WIN  0
#define OFF_BIN  49152
#define OFF_WMID 49280
#define OFF_BMID 65664
#define OFF_WOUT 65792
#define OFF_BOUT 98560
#define OFF_WSH  98816
#define OFF_BSH  197120

#define COLSZ 4718592   // 1152 * 4096 (NOT a power of 2 — true division!)

// -------- scratch --------
__device__ __align__(16) float g_kall[NB * KT];
__device__ __align__(16) __half g_pf [NB * FIN * NPIX];
__device__ __align__(16) __half g_h2f[NB * NF * NPIX];
__device__ __align__(16) __half g_w1f[NB * 128 * 384];
__device__ __align__(16) __half g_w2f[NB * 128 * 128];
__device__ __align__(16) __half g_w3f[NB * 256 * 512];
__device__ __align__(16) __half g_colf[NB * 1152 * NPIX];
__device__ __align__(16) __half g_rw1f[NB * 147456];
__device__ __align__(16) __half g_rw2f[NB * 147456];
__device__ __align__(16) float g_c2[NB * NF * NPIX];

#define CP16(dst, src) \
    asm volatile("cp.async.cg.shared.global [%0], [%1], 16;\n" :: "r"(dst), "l"(src))
#define CP_COMMIT() asm volatile("cp.async.commit_group;\n" ::: "memory")
#define CP_WAIT(n)  asm volatile("cp.async.wait_group %0;\n" :: "n"(n) : "memory")

// ======================================================================
// hyper + pack fused (weights -> single fp16 plane)
// ======================================================================
__global__ void __launch_bounds__(256) hyper_kernel(
    const float* __restrict__ lat, const float* __restrict__ hw,
    const float* __restrict__ hb, float* __restrict__ kall)
{
    __shared__ float ls[NB * LATD];
    const int tid = threadIdx.x;
    for (int i = tid; i < NB * LATD; i += 256) ls[i] = lat[i];
    __syncthreads();
    const int n = blockIdx.x * 256 + tid;
    float acc[NB];
#pragma unroll
    for (int b = 0; b < NB; b++) acc[b] = 0.f;
    for (int k = 0; k < LATD; k++) {
        float w = hw[(size_t)k * KT + n];
#pragma unroll
        for (int b = 0; b < NB; b++) acc[b] = fmaf(ls[b * LATD + k], w, acc[b]);
    }
    const float bias = hb[n];

    float s = 1.f;
    int kind;
    size_t widx = 0;
    if (n < OFF_BIN)       { s = 0.05103103630798288f; kind = 0; widx = n; }
    else if (n < OFF_WMID) { kind = 3; }
    else if (n < OFF_BMID) { s = 0.08838834764831845f; kind = 1; widx = n - OFF_WMID; }
    else if (n < OFF_WOUT) { kind = 3; }
    else if (n < OFF_BOUT) {
        s = 0.08838834764831845f; kind = 2;
        int i = n - OFF_WOUT;
        widx = (size_t)(i >> 7) * 512 + (i & 127);
    } else if (n < OFF_WSH) { kind = 3; }
    else if (n < OFF_BSH) {
        s = 0.05103103630798288f; kind = 2;
        int i = n - OFF_WSH;
        widx = (size_t)(i / 384) * 512 + 128 + (i % 384);
    } else kind = 3;

#pragma unroll
    for (int b = 0; b < NB; b++) {
        float v = (acc[b] + bias) * s;
        if (kind == 3) {
            kall[(size_t)b * KT + n] = v;
        } else {
            __half h = __float2half_rn(v);
            if (kind == 0)      g_w1f[(size_t)b * 49152 + widx] = h;
            else if (kind == 1) g_w2f[(size_t)b * 16384 + widx] = h;
            else                g_w3f[(size_t)b * 131072 + widx] = h;
        }
    }
}

// ======================================================================
// pack res-conv weights -> single fp16 plane, replicated per batch
// ======================================================================
__global__ void __launch_bounds__(256) pack_rw_kernel(
    const float* __restrict__ w, __half* __restrict__ d)
{
    const int idx = blockIdx.x * 256 + threadIdx.x;
    const int o = idx / 1152, r = idx - o * 1152;
    const int t = r >> 7, c = r & 127;
    __half h = __float2half_rn(w[o * 1152 + c * 9 + t]);
#pragma unroll
    for (int b = 0; b < NB; b++)
        d[(size_t)b * 147456 + idx] = h;
}

// ======================================================================
// im2col
// ======================================================================
__global__ void __launch_bounds__(256) im2col_f32_kernel(
    const float* __restrict__ src, __half* __restrict__ d)
{
    const size_t idx = (size_t)blockIdx.x * 256 + threadIdx.x;
    const int b = (int)(idx / COLSZ);
    const size_t r = idx - (size_t)b * COLSZ;
    const int k = (int)(r >> 12), px = (int)(r & 4095);
    const int tap = k >> 7, ch = k & 127;
    const int dy = tap / 3 - 1, dx = tap % 3 - 1;
    const int y = (px >> 6) + dy, x = (px & 63) + dx;
    float v = 0.f;
    if ((unsigned)y < 64u && (unsigned)x < 64u)
        v = src[(((size_t)b * 128 + ch) << 12) + y * 64 + x];
    d[idx] = __float2half_rn(v);
}

__global__ void __launch_bounds__(256) im2col_h_kernel(
    const __half* __restrict__ src, __half* __restrict__ d)
{
    const size_t idx = (size_t)blockIdx.x * 256 + threadIdx.x;
    const int b = (int)(idx / COLSZ);
    const size_t r = idx - (size_t)b * COLSZ;
    const int k = (int)(r >> 12), px = (int)(r & 4095);
    const int tap = k >> 7, ch = k & 127;
    const int dy = tap / 3 - 1, dx = tap % 3 - 1;
    const int y = (px >> 6) + dy, x = (px & 63) + dx;
    __half v = __float2half_rn(0.f);
    if ((unsigned)y < 64u && (unsigned)x < 64u)
        v = src[(((size_t)b * 128 + ch) << 12) + y * 64 + x];
    d[idx] = v;
}

// ======================================================================
// build_p -> single fp16 plane (plain stores; R14 pairing was neutral)
// ======================================================================
__global__ void __launch_bounds__(256) build_p_kernel(
    const float* __restrict__ X, __half* __restrict__ P)
{
    const int c = blockIdx.x, b = blockIdx.y, tid = threadIdx.x;
    __shared__ float sp[68 * 68];
    __shared__ float red[8][6];
    __shared__ float stats[6];
    for (int i = tid; i < 68 * 68; i += 256) sp[i] = 0.f;
    __syncthreads();
    const float* Xp = X + ((size_t)b * NF + c) * NPIX;
    for (int i = tid; i < NPIX; i += 256) {
        int y = i >> 6, x = i & 63;
        sp[(y + 2) * 68 + (x + 2)] = Xp[i];
    }
    __syncthreads();
    const float C = 0.70710678118654752f;
    float vx[16], vsx[16], vsy[16];
    float s0 = 0.f, q0 = 0.f, s1 = 0.f, q1 = 0.f, s2 = 0.f, q2 = 0.f;
#pragma unroll
    for (int it = 0; it < 16; it++) {
        int pix = tid + it * 256;
        int y = pix >> 6, x = pix & 63;
        const float* B = &sp[y * 68 + x];
        float xv = B[2*68+2];
        float sx = C*(B[1*68+4]-B[1*68+0]) + 0.5f*(B[1*68+3]-B[1*68+1])
                 + (B[2*68+4]-B[2*68+0]) + C*(B[2*68+3]-B[2*68+1])
                 + C*(B[3*68+4]-B[3*68+0]) + 0.5f*(B[3*68+3]-B[3*68+1]);
        float sy = C*(B[4*68+1]-B[0*68+1]) + (B[4*68+2]-B[0*68+2])
                 + C*(B[4*68+3]-B[0*68+3])
                 + 0.5f*(B[3*68+1]-B[1*68+1]) + C*(B[3*68+2]-B[1*68+2])
                 + 0.5f*(B[3*68+3]-B[1*68+3]);
        vx[it] = xv; vsx[it] = sx; vsy[it] = sy;
        s0 += xv; q0 = fmaf(xv, xv, q0);
        s1 += sx; q1 = fmaf(sx, sx, q1);
        s2 += sy; q2 = fmaf(sy, sy, q2);
    }
#pragma unroll
    for (int off = 16; off; off >>= 1) {
        s0 += __shfl_down_sync(~0u, s0, off); q0 += __shfl_down_sync(~0u, q0, off);
        s1 += __shfl_down_sync(~0u, s1, off); q1 += __shfl_down_sync(~0u, q1, off);
        s2 += __shfl_down_sync(~0u, s2, off); q2 += __shfl_down_sync(~0u, q2, off);
    }
    if ((tid & 31) == 0) {
        int w = tid >> 5;
        red[w][0]=s0; red[w][1]=q0; red[w][2]=s1; red[w][3]=q1; red[w][4]=s2; red[w][5]=q2;
    }
    __syncthreads();
    if (tid == 0) {
        float S[6] = {0,0,0,0,0,0};
        for (int w = 0; w < 8; w++) for (int j = 0; j < 6; j++) S[j] += red[w][j];
        const float invN = 1.f / 4096.f;
#pragma unroll
        for (int t3 = 0; t3 < 3; t3++) {
            float mu = S[2*t3] * invN;
            float var = fmaxf(S[2*t3+1] * invN - mu*mu, 0.f);
            stats[2*t3] = mu; stats[2*t3+1] = rsqrtf(var + 1e-5f);
        }
    }
    __syncthreads();
    const float mu0 = stats[0], in0 = stats[1], mu1 = stats[2], in1 = stats[3],
                mu2 = stats[4], in2 = stats[5];
    const size_t p0 = ((size_t)b * FIN + c) * NPIX;
#pragma unroll
    for (int it = 0; it < 16; it++) {
        int pix = tid + it * 256;
        P[p0 + pix]                      = __float2half_rn((vx[it]  - mu0) * in0);
        P[p0 + (size_t)NF*NPIX + pix]    = __float2half_rn((vsx[it] - mu1) * in1);
        P[p0 + (size_t)2*NF*NPIX + pix]  = __float2half_rn((vsy[it] - mu2) * in2);
    }
}

// ======================================================================
// FUSED g1+g2: h2 = relu(W2 @ relu(W1 @ p + b1) + b2), h1 lives in smem.
// Single fp16 weight plane, 1 MMA per fragment pair.
// ======================================================================
__global__ void __launch_bounds__(256, 2) mlp12_kernel(
    const __half* __restrict__ W1f, const __half* __restrict__ W2f,
    const __half* __restrict__ P, const float* __restrict__ kall,
    __half* __restrict__ H2out)
{
    constexpr int KCH = 16;
    constexpr int AW = 24;
    constexpr int BW = 136;
    constexpr int EW = 132;
    constexpr int A_ELEMS = 128 * AW;                // 3072
    constexpr int BUF1 = A_ELEMS + KCH * BW;         // 5248 halfs
    constexpr int BUF2 = A_ELEMS;

    extern __shared__ __align__(16) char sm[];
    __half* smH = (__half*)sm;
    float* Es = (float*)sm;
    __half* H = (__half*)(sm + 69632);

    const int tid = threadIdx.x;
    const int b = blockIdx.y;
    const int n0 = blockIdx.x * 128;
    const int wid = tid >> 5;
    const int wm = wid >> 1, wn = wid & 1;

    const __half* W1B = W1f + (size_t)b * 49152;
    const __half* W2B = W2f + (size_t)b * 16384;
    const __half* Pb = P + (size_t)b * FIN * NPIX;

    wmma::fragment<wmma::accumulator, 16, 16, 16, float> acc[2][4];
#pragma unroll
    for (int i = 0; i < 2; i++)
#pragma unroll
        for (int j = 0; j < 4; j++) wmma::fill_fragment(acc[i][j], 0.f);

    auto stage1 = [&](int kc, int s) {
        __half* Af = smH + (size_t)s * BUF1;
        __half* Bf = Af + A_ELEMS;
        {
            int m = tid >> 1, q = tid & 1;           // 128 rows x 2 pieces = 256
            const __half* src = W1B + (size_t)m * 384 + kc + q * 8;
            unsigned d = (unsigned)__cvta_generic_to_shared(Af + m * AW + q * 8);
            CP16(d, src);
        }
        {
            int k = tid >> 4, c = (tid & 15) * 8;
            const __half* src = Pb + (size_t)(kc + k) * NPIX + n0 + c;
            unsigned d = (unsigned)__cvta_generic_to_shared(Bf + k * BW + c);
            CP16(d, src);
        }
        CP_COMMIT();
    };
    auto compute1 = [&](int s) {
        const __half* Af = smH + (size_t)s * BUF1;
        const __half* Bf = Af + A_ELEMS;
        wmma::fragment<wmma::matrix_a, 16, 16, 16, __half, wmma::row_major> af[2];
        wmma::fragment<wmma::matrix_b, 16, 16, 16, __half, wmma::row_major> bf[4];
#pragma unroll
        for (int i = 0; i < 2; i++)
            wmma::load_matrix_sync(af[i], Af + (wm * 32 + i * 16) * AW, AW);
#pragma unroll
        for (int j = 0; j < 4; j++)
            wmma::load_matrix_sync(bf[j], Bf + wn * 64 + j * 16, BW);
#pragma unroll
        for (int i = 0; i < 2; i++)
#pragma unroll
            for (int j = 0; j < 4; j++)
                wmma::mma_sync(acc[i][j], af[i], bf[j], acc[i][j]);
    };

    {
        const int nch = 24;
        stage1(0, 0);
        stage1(KCH, 1);
        CP_WAIT(1);
        __syncthreads();
        for (int ic = 0; ic < nch; ic++) {
            compute1(ic % 3);
            if (ic + 2 < nch) {
                stage1((ic + 2) * KCH, (ic + 2) % 3);
                CP_WAIT(1);
            } else {
                CP_WAIT(0);
            }
            __syncthreads();
        }
    }
#pragma unroll
    for (int i = 0; i < 2; i++)
#pragma unroll
        for (int j = 0; j < 4; j++)
            wmma::store_matrix_sync(Es + (wm * 32 + i * 16) * EW + wn * 64 + j * 16,
                                    acc[i][j], EW, wmma::mem_row_major);
    __syncthreads();
    {
        const int m = tid >> 1, seg = tid & 1;
        const float bias1 = kall[(size_t)b * KT + OFF_BIN + m];
        const float* er = Es + m * EW + seg * 64;
        __half* hr = H + m * BW + seg * 64;
#pragma unroll
        for (int c = 0; c < 64; c += 2) {
            __half2 o;
            o.x = __float2half_rn(fmaxf(er[c + 0] + bias1, 0.f));
            o.y = __float2half_rn(fmaxf(er[c + 1] + bias1, 0.f));
            *reinterpret_cast<__half2*>(&hr[c]) = o;
        }
    }
    __syncthreads();

#pragma unroll
    for (int i = 0; i < 2; i++)
#pragma unroll
        for (int j = 0; j < 4; j++) wmma::fill_fragment(acc[i][j], 0.f);

    auto stage2 = [&](int kc, int s) {
        __half* Af = smH + (size_t)s * BUF2;
        int m = tid >> 1, q = tid & 1;
        const __half* src = W2B + (size_t)m * 128 + kc + q * 8;
        unsigned d = (unsigned)__cvta_generic_to_shared(Af + m * AW + q * 8);
        CP16(d, src);
        CP_COMMIT();
    };
    auto compute2 = [&](int kc, int s) {
        const __half* Af = smH + (size_t)s * BUF2;
        wmma::fragment<wmma::matrix_a, 16, 16, 16, __half, wmma::row_major> af[2];
        wmma::fragment<wmma::matrix_b, 16, 16, 16, __half, wmma::row_major> bf[4];
#pragma unroll
        for (int i = 0; i < 2; i++)
            wmma::load_matrix_sync(af[i], Af + (wm * 32 + i * 16) * AW, AW);
#pragma unroll
        for (int j = 0; j < 4; j++)
            wmma::load_matrix_sync(bf[j], H + kc * BW + wn * 64 + j * 16, BW);
#pragma unroll
        for (int i = 0; i < 2; i++)
#pragma unroll
            for (int j = 0; j < 4; j++)
                wmma::mma_sync(acc[i][j], af[i], bf[j], acc[i][j]);
    };

    {
        const int nch = 8;
        stage2(0, 0);
        stage2(KCH, 1);
        CP_WAIT(1);
        __syncthreads();
        for (int ic = 0; ic < nch; ic++) {
            compute2(ic * KCH, ic % 3);
            if (ic + 2 < nch) {
                stage2((ic + 2) * KCH, (ic + 2) % 3);
                CP_WAIT(1);
            } else {
                CP_WAIT(0);
            }
            __syncthreads();
        }
    }
#pragma unroll
    for (int i = 0; i < 2; i++)
#pragma unroll
        for (int j = 0; j < 4; j++)
            wmma::store_matrix_sync(Es + (wm * 32 + i * 16) * EW + wn * 64 + j * 16,
                                    acc[i][j], EW, wmma::mem_row_major);
    __syncthreads();
    {
        const int m = tid >> 1, seg = tid & 1;
        const float bias2 = kall[(size_t)b * KT + OFF_BMID + m];
        const size_t base = ((size_t)b * 128 + m) * NPIX + n0 + seg * 64;
        const float* er = Es + m * EW + seg * 64;
#pragma unroll
        for (int c = 0; c < 64; c += 2) {
            __half2 o;
            o.x = __float2half_rn(fmaxf(er[c + 0] + bias2, 0.f));
            o.y = __float2half_rn(fmaxf(er[c + 1] + bias2, 0.f));
            *reinterpret_cast<__half2*>(&H2out[base + c]) = o;
        }
    }
}

// ======================================================================
// wmma fp16 GEMM: single term, 3-stage / 1 sync.
// MBLKS=1 (KCH=32): conv tail; MBLKS=2 (KCH=16): g3 gated update
// ======================================================================
template<int MBLKS>
__global__ void __launch_bounds__(256, 2) gemm_wmma(
    const __half* __restrict__ Wf, int Ktot,
    const __half* __restrict__ B1, int K1, const __half* __restrict__ B2,
    const float* __restrict__ kall, int boff1, int boff2,
    const float* __restrict__ bias_dir,
    float* __restrict__ outf, __half* __restrict__ outh,
    const float* __restrict__ xold, const float* __restrict__ leakp)
{
    constexpr int MT = MBLKS * 128;
    constexpr int NT = 128 / MBLKS;
    constexpr int KCH = (MBLKS == 1) ? 32 : 16;
    constexpr int KK = KCH / 16;
    constexpr int AP = KCH / 8;
    constexpr int AW = KCH + 8;
    constexpr int BW = (MBLKS == 1) ? 136 : 72;
    constexpr int EW = NT + 4;
    constexpr int BUFE = MT * AW + KCH * BW;

    extern __shared__ __align__(16) char sm[];
    __half* smB = (__half*)sm;
    float* Es = (float*)sm;

    const int tid = threadIdx.x;
    const int b = blockIdx.y;
    const int n0 = blockIdx.x * NT;
    const int wid = tid >> 5;
    const int wm = (MBLKS == 1) ? (wid >> 1) : wid;
    const int wn = (MBLKS == 1) ? (wid & 1) : 0;

    const __half* WB = Wf + (size_t)b * MT * Ktot;

    wmma::fragment<wmma::accumulator, 16, 16, 16, float> acc[2][4];
#pragma unroll
    for (int i = 0; i < 2; i++)
#pragma unroll
        for (int j = 0; j < 4; j++) wmma::fill_fragment(acc[i][j], 0.f);

    auto stage = [&](int kc, int s) {
        __half* Af = smB + (size_t)s * BUFE;
        __half* Bf = Af + MT * AW;
#pragma unroll
        for (int i = tid; i < MT * AP; i += 256) {
            int m = i / AP, q = i - m * AP;
            const __half* src = WB + (size_t)m * Ktot + kc + q * 8;
            unsigned d = (unsigned)__cvta_generic_to_shared(Af + m * AW + q * 8);
            CP16(d, src);
        }
        const __half* sf; int ch0;
        if (kc < K1) { sf = B1 + (size_t)b * K1 * NPIX; ch0 = kc; }
        else { sf = B2 + (size_t)b * (Ktot - K1) * NPIX; ch0 = kc - K1; }
        constexpr int NC8 = NT / 8;
#pragma unroll
        for (int i = tid; i < KCH * NC8; i += 256) {
            int k = i / NC8, c = (i - k * NC8) * 8;
            const __half* src = sf + (size_t)(ch0 + k) * NPIX + n0 + c;
            unsigned d = (unsigned)__cvta_generic_to_shared(Bf + k * BW + c);
            CP16(d, src);
        }
        CP_COMMIT();
    };

    auto compute = [&](int s) {
        const __half* Af = smB + (size_t)s * BUFE;
        const __half* Bf = Af + MT * AW;
#pragma unroll
        for (int kk = 0; kk < KK; kk++) {
            wmma::fragment<wmma::matrix_a, 16, 16, 16, __half, wmma::row_major> af[2];
            wmma::fragment<wmma::matrix_b, 16, 16, 16, __half, wmma::row_major> bf[4];
#pragma unroll
            for (int i = 0; i < 2; i++)
                wmma::load_matrix_sync(af[i], Af + (wm * 32 + i * 16) * AW + kk * 16, AW);
#pragma unroll
            for (int j = 0; j < 4; j++)
                wmma::load_matrix_sync(bf[j], Bf + kk * 16 * BW + wn * 64 + j * 16, BW);
#pragma unroll
            for (int i = 0; i < 2; i++)
#pragma unroll
                for (int j = 0; j < 4; j++)
                    wmma::mma_sync(acc[i][j], af[i], bf[j], acc[i][j]);
        }
    };

    const int nch = Ktot / KCH;
    stage(0, 0);
    stage(KCH, 1);
    CP_WAIT(1);
    __syncthreads();
    for (int ic = 0; ic < nch; ic++) {
        compute(ic % 3);
        if (ic + 2 < nch) {
            stage((ic + 2) * KCH, (ic + 2) % 3);
            CP_WAIT(1);
        } else {
            CP_WAIT(0);
        }
        __syncthreads();
    }

#pragma unroll
    for (int i = 0; i < 2; i++)
#pragma unroll
        for (int j = 0; j < 4; j++)
            wmma::store_matrix_sync(Es + (wm * 32 + i * 16) * EW + wn * 64 + j * 16,
                                    acc[i][j], EW, wmma::mem_row_major);
    __syncthreads();

    const int m = tid >> 1, seg = tid & 1;
    if (MBLKS == 1) {
        const float bias = kall ? kall[(size_t)b * KT + boff1 + m] : bias_dir[m];
        const size_t base = ((size_t)b * 128 + m) * NPIX + n0 + seg * 64;
        const float* er = Es + m * EW + seg * 64;
        if (outh) {
#pragma unroll
            for (int c = 0; c < 64; c += 2) {
                __half2 o;
                o.x = __float2half_rn(fmaxf(er[c + 0] + bias, 0.f));
                o.y = __float2half_rn(fmaxf(er[c + 1] + bias, 0.f));
                *reinterpret_cast<__half2*>(&outh[base + c]) = o;
            }
        } else {
#pragma unroll
            for (int c = 0; c < 64; c += 4) {
                float4 o;
                o.x = er[c+0] + bias; o.y = er[c+1] + bias;
                o.z = er[c+2] + bias; o.w = er[c+3] + bias;
                if (xold) {
                    float4 x = *reinterpret_cast<const float4*>(&xold[base + c]);
                    o.x += x.x; o.y += x.y; o.z += x.z; o.w += x.w;
                }
                *reinterpret_cast<float4*>(&outf[base + c]) = o;
            }
        }
    } else {
        const float leak = fminf(fmaxf(leakp[0], 0.001f), 1000.f);
        const float* ka = kall + (size_t)b * KT;
        const float bv = ka[boff1 + m] + ka[boff2 + m];
        const float bg = ka[boff1 + 128 + m] + ka[boff2 + 128 + m];
        const size_t base = ((size_t)b * 128 + m) * NPIX + n0 + seg * 32;
        const float* ev = Es + m * EW + seg * 32;
        const float* eg = Es + (m + 128) * EW + seg * 32;
#pragma unroll
        for (int c = 0; c < 32; c += 4) {
            float4 x = *reinterpret_cast<const float4*>(&xold[base + c]);
            float4 o;
            { float v = ev[c+0] + bv, g = eg[c+0] + bg; o.x = x.x + leak * v / (1.f + __expf(-g)); }
            { float v = ev[c+1] + bv, g = eg[c+1] + bg; o.y = x.y + leak * v / (1.f + __expf(-g)); }
            { float v = ev[c+2] + bv, g = eg[c+2] + bg; o.z = x.z + leak * v / (1.f + __expf(-g)); }
            { float v = ev[c+3] + bv, g = eg[c+3] + bg; o.w = x.w + leak * v / (1.f + __expf(-g)); }
            *reinterpret_cast<float4*>(&outf[base + c]) = o;
        }
    }
}

// ======================================================================
// final 128->3 conv + clip
// ======================================================================
__global__ void __launch_bounds__(256) conv_img_kernel(
    const float* __restrict__ X, const float* __restrict__ W,
    const float* __restrict__ bias,
    float* __restrict__ out_img, float* __restrict__ out_raw)
{
    const int b = blockIdx.y, y0 = blockIdx.x * 4, tid = threadIdx.x;
    const int r = tid >> 6, x = tid & 63;
    __shared__ float sW[3 * 1152];
    __shared__ float sIn[6][66];
    for (int i = tid; i < 3 * 1152; i += 256) sW[i] = W[i];
    float acc[3] = {0.f, 0.f, 0.f};
    const float* Xb = X + (size_t)b * NF * NPIX;
    for (int ci = 0; ci < NF; ci++) {
        __syncthreads();
        for (int i = tid; i < 6 * 66; i += 256) {
            int ry = i / 66, cx = i - ry * 66;
            int gy = y0 - 1 + ry, gx = cx - 1;
            float v = 0.f;
            if ((unsigned)gy < 64u && (unsigned)gx < 64u)
                v = Xb[(size_t)ci * NPIX + gy * 64 + gx];
            sIn[ry][cx] = v;
        }
        __syncthreads();
        float in[9];
#pragma unroll
        for (int dy = 0; dy < 3; dy++)
#pragma unroll
            for (int dx = 0; dx < 3; dx++) in[dy * 3 + dx] = sIn[r + dy][x + dx];
#pragma unroll
        for (int o = 0; o < 3; o++)
#pragma unroll
            for (int j = 0; j < 9; j++)
                acc[o] = fmaf(in[j], sW[o * 1152 + ci * 9 + j], acc[o]);
    }
#pragma unroll
    for (int o = 0; o < 3; o++) {
        float v = acc[o] + bias[o];
        size_t idx = ((size_t)b * 3 + o) * NPIX + (size_t)(y0 + r) * 64 + x;
        out_raw[idx] = v;
        out_img[idx] = fminf(fmaxf(v, -1.f), 1.f);
    }
}

// ======================================================================
extern "C" void kernel_launch(void* const* d_in, const int* in_sizes, int n_in,
                              void* d_out, int out_size)
{
    const float* lat  = (const float*)d_in[0];
    const float* ca   = (const float*)d_in[1];
    const float* leak = (const float*)d_in[2];
    const float* hw   = (const float*)d_in[3];
    const float* hb   = (const float*)d_in[4];
    const float* rw1  = (const float*)d_in[5];
    const float* rb1  = (const float*)d_in[6];
    const float* rw2  = (const float*)d_in[7];
    const float* rb2  = (const float*)d_in[8];
    const float* iw   = (const float*)d_in[9];
    const float* ib   = (const float*)d_in[10];

    float* out = (float*)d_out;
    float* out_img = out;
    float* embs    = out + 98304;
    float* out_raw = out + 98304 + (size_t)17 * 4194304;

    float *kall, *c2;
    __half *pf, *h2f, *colf, *w1f, *w2f, *w3f, *r1f, *r2f;
    cudaGetSymbolAddress((void**)&kall, g_kall);
    cudaGetSymbolAddress((void**)&pf,  g_pf);
    cudaGetSymbolAddress((void**)&h2f, g_h2f);
    cudaGetSymbolAddress((void**)&w1f, g_w1f);
    cudaGetSymbolAddress((void**)&w2f, g_w2f);
    cudaGetSymbolAddress((void**)&w3f, g_w3f);
    cudaGetSymbolAddress((void**)&colf, g_colf);
    cudaGetSymbolAddress((void**)&r1f, g_rw1f);
    cudaGetSymbolAddress((void**)&r2f, g_rw2f);
    cudaGetSymbolAddress((void**)&c2, g_c2);

    // gemm<1>: stage = (128*40 + 32*136)*2B = 18944; 3x = 56832 < Es 67584
    // gemm<2>: stage = (256*24 + 16*72)*2B  = 14592; 3x = 43776 < Es 69632
    const int SM1 = 67584;
    const int SM2 = 69632;
    const int SMF = 104448;  // mlp12: region A 69632 + H 34816
    cudaFuncSetAttribute(gemm_wmma<1>, cudaFuncAttributeMaxDynamicSharedMemorySize, SM1);
    cudaFuncSetAttribute(gemm_wmma<2>, cudaFuncAttributeMaxDynamicSharedMemorySize, SM2);
    cudaFuncSetAttribute(mlp12_kernel, cudaFuncAttributeMaxDynamicSharedMemorySize, SMF);

    hyper_kernel<<<KT / 256, 256>>>(lat, hw, hb, kall);
    pack_rw_kernel<<<576, 256>>>(rw1, r1f);
    pack_rw_kernel<<<576, 256>>>(rw2, r2f);
    cudaMemcpyAsync(embs, ca, (size_t)4194304 * sizeof(float), cudaMemcpyDeviceToDevice);

    for (int t = 0; t < NCALLS; t++) {
        float* x  = embs + (size_t)t * 4194304;
        float* xn = x + 4194304;

        build_p_kernel<<<dim3(NF, NB), 256>>>(x, pf);
        mlp12_kernel<<<dim3(32, NB), 256, SMF>>>(w1f, w2f, pf, kall, h2f);
        gemm_wmma<2><<<dim3(64, NB), 256, SM2>>>(
            w3f, 512, h2f, 128, pf,
            kall, OFF_BOUT, OFF_BSH, nullptr, xn, nullptr, x, leak);
    }

    float* xf = embs + (size_t)NCALLS * 4194304;
    im2col_f32_kernel<<<147456, 256>>>(xf, colf);
    gemm_wmma<1><<<dim3(32, NB), 256, SM1>>>(
        r1f, 1152, colf, 1152, nullptr,
        nullptr, 0, 0, rb1, nullptr, pf, nullptr, nullptr);
    im2col_h_kernel<<<147456, 256>>>(pf, colf);
    gemm_wmma<1><<<dim3(32, NB), 256, SM1>>>(
        r2f, 1152, colf, 1152, nullptr,
        nullptr, 0, 0, rb2, c2, nullptr, xf, nullptr);
    conv_img_kernel<<<dim3(16, NB), 256>>>(c2, iw, ib, out_img, out_raw);
}

// round 16
// speedup vs baseline: 1.4932x; 1.0941x over previous
#include <cuda_runtime.h>
#include <cuda_fp16.h>
#include <mma.h>
#include <math.h>

using namespace nvcuda;

#define NB 8
#define NF 128
#define LATD 256
#define NPIX 4096
#define NCALLS 16
#define FIN 384
#define KT 197376

#define OFF_WIN  0
#define OFF_BIN  49152
#define OFF_WMID 49280
#define OFF_BMID 65664
#define OFF_WOUT 65792
#define OFF_BOUT 98560
#define OFF_WSH  98816
#define OFF_BSH  197120

#define COLSZ 4718592   // 1152 * 4096 (NOT a power of 2 — true division!)

// -------- scratch --------
__device__ __align__(16) float g_kall[NB * KT];
__device__ __align__(16) __half g_pf [NB * FIN * NPIX];
__device__ __align__(16) __half g_h2f[NB * NF * NPIX];
__device__ __align__(16) __half g_w1f[NB * 128 * 384];
__device__ __align__(16) __half g_w2f[NB * 128 * 128];
__device__ __align__(16) __half g_w3f[NB * 256 * 512];
__device__ __align__(16) __half g_colf[NB * 1152 * NPIX];
__device__ __align__(16) __half g_rw1f[NB * 147456];
__device__ __align__(16) __half g_rw2f[NB * 147456];
__device__ __align__(16) float g_c2[NB * NF * NPIX];

#define CP16(dst, src) \
    asm volatile("cp.async.cg.shared.global [%0], [%1], 16;\n" :: "r"(dst), "l"(src))
#define CP_COMMIT() asm volatile("cp.async.commit_group;\n" ::: "memory")
#define CP_WAIT(n)  asm volatile("cp.async.wait_group %0;\n" :: "n"(n) : "memory")

// ======================================================================
// hyper + pack fused (weights -> single fp16 plane)
// ======================================================================
__global__ void __launch_bounds__(256) hyper_kernel(
    const float* __restrict__ lat, const float* __restrict__ hw,
    const float* __restrict__ hb, float* __restrict__ kall)
{
    __shared__ float ls[NB * LATD];
    const int tid = threadIdx.x;
    for (int i = tid; i < NB * LATD; i += 256) ls[i] = lat[i];
    __syncthreads();
    const int n = blockIdx.x * 256 + tid;
    float acc[NB];
#pragma unroll
    for (int b = 0; b < NB; b++) acc[b] = 0.f;
    for (int k = 0; k < LATD; k++) {
        float w = hw[(size_t)k * KT + n];
#pragma unroll
        for (int b = 0; b < NB; b++) acc[b] = fmaf(ls[b * LATD + k], w, acc[b]);
    }
    const float bias = hb[n];

    float s = 1.f;
    int kind;
    size_t widx = 0;
    if (n < OFF_BIN)       { s = 0.05103103630798288f; kind = 0; widx = n; }
    else if (n < OFF_WMID) { kind = 3; }
    else if (n < OFF_BMID) { s = 0.08838834764831845f; kind = 1; widx = n - OFF_WMID; }
    else if (n < OFF_WOUT) { kind = 3; }
    else if (n < OFF_BOUT) {
        s = 0.08838834764831845f; kind = 2;
        int i = n - OFF_WOUT;
        widx = (size_t)(i >> 7) * 512 + (i & 127);
    } else if (n < OFF_WSH) { kind = 3; }
    else if (n < OFF_BSH) {
        s = 0.05103103630798288f; kind = 2;
        int i = n - OFF_WSH;
        widx = (size_t)(i / 384) * 512 + 128 + (i % 384);
    } else kind = 3;

#pragma unroll
    for (int b = 0; b < NB; b++) {
        float v = (acc[b] + bias) * s;
        if (kind == 3) {
            kall[(size_t)b * KT + n] = v;
        } else {
            __half h = __float2half_rn(v);
            if (kind == 0)      g_w1f[(size_t)b * 49152 + widx] = h;
            else if (kind == 1) g_w2f[(size_t)b * 16384 + widx] = h;
            else                g_w3f[(size_t)b * 131072 + widx] = h;
        }
    }
}

// ======================================================================
// pack res-conv weights -> single fp16 plane, replicated per batch
// ======================================================================
__global__ void __launch_bounds__(256) pack_rw_kernel(
    const float* __restrict__ w, __half* __restrict__ d)
{
    const int idx = blockIdx.x * 256 + threadIdx.x;
    const int o = idx / 1152, r = idx - o * 1152;
    const int t = r >> 7, c = r & 127;
    __half h = __float2half_rn(w[o * 1152 + c * 9 + t]);
#pragma unroll
    for (int b = 0; b < NB; b++)
        d[(size_t)b * 147456 + idx] = h;
}

// ======================================================================
// im2col, 8 px per thread, 16B stores (values identical to scalar version)
// ======================================================================
__global__ void __launch_bounds__(256) im2col_f32_kernel(
    const float* __restrict__ src, __half* __restrict__ d)
{
    const size_t idx = ((size_t)blockIdx.x * 256 + threadIdx.x) * 8;
    const int b = (int)(idx / COLSZ);
    const size_t r = idx - (size_t)b * COLSZ;
    const int k = (int)(r >> 12), px0 = (int)(r & 4095);
    const int tap = k >> 7, ch = k & 127;
    const int dy = tap / 3 - 1, dx = tap % 3 - 1;
    const int y = (px0 >> 6) + dy;
    const float* srow = src + (((size_t)b * 128 + ch) << 12) + y * 64;
    const bool yok = (unsigned)y < 64u;
    __half o[8];
#pragma unroll
    for (int i = 0; i < 8; i++) {
        int x = (px0 & 63) + i + dx;
        float v = (yok && (unsigned)x < 64u) ? srow[x] : 0.f;
        o[i] = __float2half_rn(v);
    }
    *reinterpret_cast<uint4*>(&d[idx]) = *reinterpret_cast<uint4*>(o);
}

__global__ void __launch_bounds__(256) im2col_h_kernel(
    const __half* __restrict__ src, __half* __restrict__ d)
{
    const size_t idx = ((size_t)blockIdx.x * 256 + threadIdx.x) * 8;
    const int b = (int)(idx / COLSZ);
    const size_t r = idx - (size_t)b * COLSZ;
    const int k = (int)(r >> 12), px0 = (int)(r & 4095);
    const int tap = k >> 7, ch = k & 127;
    const int dy = tap / 3 - 1, dx = tap % 3 - 1;
    const int y = (px0 >> 6) + dy;
    const __half* srow = src + (((size_t)b * 128 + ch) << 12) + y * 64;
    const bool yok = (unsigned)y < 64u;
    __half o[8];
#pragma unroll
    for (int i = 0; i < 8; i++) {
        int x = (px0 & 63) + i + dx;
        o[i] = (yok && (unsigned)x < 64u) ? srow[x] : __float2half_rn(0.f);
    }
    *reinterpret_cast<uint4*>(&d[idx]) = *reinterpret_cast<uint4*>(o);
}

// ======================================================================
// build_p -> single fp16 plane
// ======================================================================
__global__ void __launch_bounds__(256) build_p_kernel(
    const float* __restrict__ X, __half* __restrict__ P)
{
    const int c = blockIdx.x, b = blockIdx.y, tid = threadIdx.x;
    __shared__ float sp[68 * 68];
    __shared__ float red[8][6];
    __shared__ float stats[6];
    for (int i = tid; i < 68 * 68; i += 256) sp[i] = 0.f;
    __syncthreads();
    const float* Xp = X + ((size_t)b * NF + c) * NPIX;
    for (int i = tid; i < NPIX; i += 256) {
        int y = i >> 6, x = i & 63;
        sp[(y + 2) * 68 + (x + 2)] = Xp[i];
    }
    __syncthreads();
    const float C = 0.70710678118654752f;
    float vx[16], vsx[16], vsy[16];
    float s0 = 0.f, q0 = 0.f, s1 = 0.f, q1 = 0.f, s2 = 0.f, q2 = 0.f;
#pragma unroll
    for (int it = 0; it < 16; it++) {
        int pix = tid + it * 256;
        int y = pix >> 6, x = pix & 63;
        const float* B = &sp[y * 68 + x];
        float xv = B[2*68+2];
        float sx = C*(B[1*68+4]-B[1*68+0]) + 0.5f*(B[1*68+3]-B[1*68+1])
                 + (B[2*68+4]-B[2*68+0]) + C*(B[2*68+3]-B[2*68+1])
                 + C*(B[3*68+4]-B[3*68+0]) + 0.5f*(B[3*68+3]-B[3*68+1]);
        float sy = C*(B[4*68+1]-B[0*68+1]) + (B[4*68+2]-B[0*68+2])
                 + C*(B[4*68+3]-B[0*68+3])
                 + 0.5f*(B[3*68+1]-B[1*68+1]) + C*(B[3*68+2]-B[1*68+2])
                 + 0.5f*(B[3*68+3]-B[1*68+3]);
        vx[it] = xv; vsx[it] = sx; vsy[it] = sy;
        s0 += xv; q0 = fmaf(xv, xv, q0);
        s1 += sx; q1 = fmaf(sx, sx, q1);
        s2 += sy; q2 = fmaf(sy, sy, q2);
    }
#pragma unroll
    for (int off = 16; off; off >>= 1) {
        s0 += __shfl_down_sync(~0u, s0, off); q0 += __shfl_down_sync(~0u, q0, off);
        s1 += __shfl_down_sync(~0u, s1, off); q1 += __shfl_down_sync(~0u, q1, off);
        s2 += __shfl_down_sync(~0u, s2, off); q2 += __shfl_down_sync(~0u, q2, off);
    }
    if ((tid & 31) == 0) {
        int w = tid >> 5;
        red[w][0]=s0; red[w][1]=q0; red[w][2]=s1; red[w][3]=q1; red[w][4]=s2; red[w][5]=q2;
    }
    __syncthreads();
    if (tid == 0) {
        float S[6] = {0,0,0,0,0,0};
        for (int w = 0; w < 8; w++) for (int j = 0; j < 6; j++) S[j] += red[w][j];
        const float invN = 1.f / 4096.f;
#pragma unroll
        for (int t3 = 0; t3 < 3; t3++) {
            float mu = S[2*t3] * invN;
            float var = fmaxf(S[2*t3+1] * invN - mu*mu, 0.f);
            stats[2*t3] = mu; stats[2*t3+1] = rsqrtf(var + 1e-5f);
        }
    }
    __syncthreads();
    const float mu0 = stats[0], in0 = stats[1], mu1 = stats[2], in1 = stats[3],
                mu2 = stats[4], in2 = stats[5];
    const size_t p0 = ((size_t)b * FIN + c) * NPIX;
#pragma unroll
    for (int it = 0; it < 16; it++) {
        int pix = tid + it * 256;
        P[p0 + pix]                      = __float2half_rn((vx[it]  - mu0) * in0);
        P[p0 + (size_t)NF*NPIX + pix]    = __float2half_rn((vsx[it] - mu1) * in1);
        P[p0 + (size_t)2*NF*NPIX + pix]  = __float2half_rn((vsy[it] - mu2) * in2);
    }
}

// ======================================================================
// FUSED g1+g2: h2 = relu(W2 @ relu(W1 @ p + b1) + b2), h1 lives in smem.
// ======================================================================
__global__ void __launch_bounds__(256, 2) mlp12_kernel(
    const __half* __restrict__ W1f, const __half* __restrict__ W2f,
    const __half* __restrict__ P, const float* __restrict__ kall,
    __half* __restrict__ H2out)
{
    constexpr int KCH = 16;
    constexpr int AW = 24;
    constexpr int BW = 136;
    constexpr int EW = 132;
    constexpr int A_ELEMS = 128 * AW;
    constexpr int BUF1 = A_ELEMS + KCH * BW;
    constexpr int BUF2 = A_ELEMS;

    extern __shared__ __align__(16) char sm[];
    __half* smH = (__half*)sm;
    float* Es = (float*)sm;
    __half* H = (__half*)(sm + 69632);

    const int tid = threadIdx.x;
    const int b = blockIdx.y;
    const int n0 = blockIdx.x * 128;
    const int wid = tid >> 5;
    const int wm = wid >> 1, wn = wid & 1;

    const __half* W1B = W1f + (size_t)b * 49152;
    const __half* W2B = W2f + (size_t)b * 16384;
    const __half* Pb = P + (size_t)b * FIN * NPIX;

    wmma::fragment<wmma::accumulator, 16, 16, 16, float> acc[2][4];
#pragma unroll
    for (int i = 0; i < 2; i++)
#pragma unroll
        for (int j = 0; j < 4; j++) wmma::fill_fragment(acc[i][j], 0.f);

    auto stage1 = [&](int kc, int s) {
        __half* Af = smH + (size_t)s * BUF1;
        __half* Bf = Af + A_ELEMS;
        {
            int m = tid >> 1, q = tid & 1;
            const __half* src = W1B + (size_t)m * 384 + kc + q * 8;
            unsigned d = (unsigned)__cvta_generic_to_shared(Af + m * AW + q * 8);
            CP16(d, src);
        }
        {
            int k = tid >> 4, c = (tid & 15) * 8;
            const __half* src = Pb + (size_t)(kc + k) * NPIX + n0 + c;
            unsigned d = (unsigned)__cvta_generic_to_shared(Bf + k * BW + c);
            CP16(d, src);
        }
        CP_COMMIT();
    };
    auto compute1 = [&](int s) {
        const __half* Af = smH + (size_t)s * BUF1;
        const __half* Bf = Af + A_ELEMS;
        wmma::fragment<wmma::matrix_a, 16, 16, 16, __half, wmma::row_major> af[2];
        wmma::fragment<wmma::matrix_b, 16, 16, 16, __half, wmma::row_major> bf[4];
#pragma unroll
        for (int i = 0; i < 2; i++)
            wmma::load_matrix_sync(af[i], Af + (wm * 32 + i * 16) * AW, AW);
#pragma unroll
        for (int j = 0; j < 4; j++)
            wmma::load_matrix_sync(bf[j], Bf + wn * 64 + j * 16, BW);
#pragma unroll
        for (int i = 0; i < 2; i++)
#pragma unroll
            for (int j = 0; j < 4; j++)
                wmma::mma_sync(acc[i][j], af[i], bf[j], acc[i][j]);
    };

    {
        const int nch = 24;
        stage1(0, 0);
        stage1(KCH, 1);
        CP_WAIT(1);
        __syncthreads();
        for (int ic = 0; ic < nch; ic++) {
            compute1(ic % 3);
            if (ic + 2 < nch) {
                stage1((ic + 2) * KCH, (ic + 2) % 3);
                CP_WAIT(1);
            } else {
                CP_WAIT(0);
            }
            __syncthreads();
        }
    }
#pragma unroll
    for (int i = 0; i < 2; i++)
#pragma unroll
        for (int j = 0; j < 4; j++)
            wmma::store_matrix_sync(Es + (wm * 32 + i * 16) * EW + wn * 64 + j * 16,
                                    acc[i][j], EW, wmma::mem_row_major);
    __syncthreads();
    {
        const int m = tid >> 1, seg = tid & 1;
        const float bias1 = kall[(size_t)b * KT + OFF_BIN + m];
        const float* er = Es + m * EW + seg * 64;
        __half* hr = H + m * BW + seg * 64;
#pragma unroll
        for (int c = 0; c < 64; c += 2) {
            __half2 o;
            o.x = __float2half_rn(fmaxf(er[c + 0] + bias1, 0.f));
            o.y = __float2half_rn(fmaxf(er[c + 1] + bias1, 0.f));
            *reinterpret_cast<__half2*>(&hr[c]) = o;
        }
    }
    __syncthreads();

#pragma unroll
    for (int i = 0; i < 2; i++)
#pragma unroll
        for (int j = 0; j < 4; j++) wmma::fill_fragment(acc[i][j], 0.f);

    auto stage2 = [&](int kc, int s) {
        __half* Af = smH + (size_t)s * BUF2;
        int m = tid >> 1, q = tid & 1;
        const __half* src = W2B + (size_t)m * 128 + kc + q * 8;
        unsigned d = (unsigned)__cvta_generic_to_shared(Af + m * AW + q * 8);
        CP16(d, src);
        CP_COMMIT();
    };
    auto compute2 = [&](int kc, int s) {
        const __half* Af = smH + (size_t)s * BUF2;
        wmma::fragment<wmma::matrix_a, 16, 16, 16, __half, wmma::row_major> af[2];
        wmma::fragment<wmma::matrix_b, 16, 16, 16, __half, wmma::row_major> bf[4];
#pragma unroll
        for (int i = 0; i < 2; i++)
            wmma::load_matrix_sync(af[i], Af + (wm * 32 + i * 16) * AW, AW);
#pragma unroll
        for (int j = 0; j < 4; j++)
            wmma::load_matrix_sync(bf[j], H + kc * BW + wn * 64 + j * 16, BW);
#pragma unroll
        for (int i = 0; i < 2; i++)
#pragma unroll
            for (int j = 0; j < 4; j++)
                wmma::mma_sync(acc[i][j], af[i], bf[j], acc[i][j]);
    };

    {
        const int nch = 8;
        stage2(0, 0);
        stage2(KCH, 1);
        CP_WAIT(1);
        __syncthreads();
        for (int ic = 0; ic < nch; ic++) {
            compute2(ic * KCH, ic % 3);
            if (ic + 2 < nch) {
                stage2((ic + 2) * KCH, (ic + 2) % 3);
                CP_WAIT(1);
            } else {
                CP_WAIT(0);
            }
            __syncthreads();
        }
    }
#pragma unroll
    for (int i = 0; i < 2; i++)
#pragma unroll
        for (int j = 0; j < 4; j++)
            wmma::store_matrix_sync(Es + (wm * 32 + i * 16) * EW + wn * 64 + j * 16,
                                    acc[i][j], EW, wmma::mem_row_major);
    __syncthreads();
    {
        const int m = tid >> 1, seg = tid & 1;
        const float bias2 = kall[(size_t)b * KT + OFF_BMID + m];
        const size_t base = ((size_t)b * 128 + m) * NPIX + n0 + seg * 64;
        const float* er = Es + m * EW + seg * 64;
#pragma unroll
        for (int c = 0; c < 64; c += 2) {
            __half2 o;
            o.x = __float2half_rn(fmaxf(er[c + 0] + bias2, 0.f));
            o.y = __float2half_rn(fmaxf(er[c + 1] + bias2, 0.f));
            *reinterpret_cast<__half2*>(&H2out[base + c]) = o;
        }
    }
}

// ======================================================================
// wmma fp16 GEMM: single term, 3-stage / 1 sync, KCH=32 for both variants.
// MBLKS=1: conv tail; MBLKS=2: g3 gated update
// ======================================================================
template<int MBLKS>
__global__ void __launch_bounds__(256, 2) gemm_wmma(
    const __half* __restrict__ Wf, int Ktot,
    const __half* __restrict__ B1, int K1, const __half* __restrict__ B2,
    const float* __restrict__ kall, int boff1, int boff2,
    const float* __restrict__ bias_dir,
    float* __restrict__ outf, __half* __restrict__ outh,
    const float* __restrict__ xold, const float* __restrict__ leakp)
{
    constexpr int MT = MBLKS * 128;
    constexpr int NT = 128 / MBLKS;
    constexpr int KCH = 32;
    constexpr int KK = 2;
    constexpr int AP = 4;
    constexpr int AW = 40;
    constexpr int BW = (MBLKS == 1) ? 136 : 72;
    constexpr int EW = NT + 4;
    constexpr int BUFE = MT * AW + KCH * BW;

    extern __shared__ __align__(16) char sm[];
    __half* smB = (__half*)sm;
    float* Es = (float*)sm;

    const int tid = threadIdx.x;
    const int b = blockIdx.y;
    const int n0 = blockIdx.x * NT;
    const int wid = tid >> 5;
    const int wm = (MBLKS == 1) ? (wid >> 1) : wid;
    const int wn = (MBLKS == 1) ? (wid & 1) : 0;

    const __half* WB = Wf + (size_t)b * MT * Ktot;

    wmma::fragment<wmma::accumulator, 16, 16, 16, float> acc[2][4];
#pragma unroll
    for (int i = 0; i < 2; i++)
#pragma unroll
        for (int j = 0; j < 4; j++) wmma::fill_fragment(acc[i][j], 0.f);

    auto stage = [&](int kc, int s) {
        __half* Af = smB + (size_t)s * BUFE;
        __half* Bf = Af + MT * AW;
#pragma unroll
        for (int i = tid; i < MT * AP; i += 256) {
            int m = i / AP, q = i - m * AP;
            const __half* src = WB + (size_t)m * Ktot + kc + q * 8;
            unsigned d = (unsigned)__cvta_generic_to_shared(Af + m * AW + q * 8);
            CP16(d, src);
        }
        const __half* sf; int ch0;
        if (kc < K1) { sf = B1 + (size_t)b * K1 * NPIX; ch0 = kc; }
        else { sf = B2 + (size_t)b * (Ktot - K1) * NPIX; ch0 = kc - K1; }
        constexpr int NC8 = NT / 8;
#pragma unroll
        for (int i = tid; i < KCH * NC8; i += 256) {
            int k = i / NC8, c = (i - k * NC8) * 8;
            const __half* src = sf + (size_t)(ch0 + k) * NPIX + n0 + c;
            unsigned d = (unsigned)__cvta_generic_to_shared(Bf + k * BW + c);
            CP16(d, src);
        }
        CP_COMMIT();
    };

    auto compute = [&](int s) {
        const __half* Af = smB + (size_t)s * BUFE;
        const __half* Bf = Af + MT * AW;
#pragma unroll
        for (int kk = 0; kk < KK; kk++) {
            wmma::fragment<wmma::matrix_a, 16, 16, 16, __half, wmma::row_major> af[2];
            wmma::fragment<wmma::matrix_b, 16, 16, 16, __half, wmma::row_major> bf[4];
#pragma unroll
            for (int i = 0; i < 2; i++)
                wmma::load_matrix_sync(af[i], Af + (wm * 32 + i * 16) * AW + kk * 16, AW);
#pragma unroll
            for (int j = 0; j < 4; j++)
                wmma::load_matrix_sync(bf[j], Bf + kk * 16 * BW + wn * 64 + j * 16, BW);
#pragma unroll
            for (int i = 0; i < 2; i++)
#pragma unroll
                for (int j = 0; j < 4; j++)
                    wmma::mma_sync(acc[i][j], af[i], bf[j], acc[i][j]);
        }
    };

    const int nch = Ktot / KCH;
    stage(0, 0);
    stage(KCH, 1);
    CP_WAIT(1);
    __syncthreads();
    for (int ic = 0; ic < nch; ic++) {
        compute(ic % 3);
        if (ic + 2 < nch) {
            stage((ic + 2) * KCH, (ic + 2) % 3);
            CP_WAIT(1);
        } else {
            CP_WAIT(0);
        }
        __syncthreads();
    }

#pragma unroll
    for (int i = 0; i < 2; i++)
#pragma unroll
        for (int j = 0; j < 4; j++)
            wmma::store_matrix_sync(Es + (wm * 32 + i * 16) * EW + wn * 64 + j * 16,
                                    acc[i][j], EW, wmma::mem_row_major);
    __syncthreads();

    const int m = tid >> 1, seg = tid & 1;
    if (MBLKS == 1) {
        const float bias = kall ? kall[(size_t)b * KT + boff1 + m] : bias_dir[m];
        const size_t base = ((size_t)b * 128 + m) * NPIX + n0 + seg * 64;
        const float* er = Es + m * EW + seg * 64;
        if (outh) {
#pragma unroll
            for (int c = 0; c < 64; c += 2) {
                __half2 o;
                o.x = __float2half_rn(fmaxf(er[c + 0] + bias, 0.f));
                o.y = __float2half_rn(fmaxf(er[c + 1] + bias, 0.f));
                *reinterpret_cast<__half2*>(&outh[base + c]) = o;
            }
        } else {
#pragma unroll
            for (int c = 0; c < 64; c += 4) {
                float4 o;
                o.x = er[c+0] + bias; o.y = er[c+1] + bias;
                o.z = er[c+2] + bias; o.w = er[c+3] + bias;
                if (xold) {
                    float4 x = *reinterpret_cast<const float4*>(&xold[base + c]);
                    o.x += x.x; o.y += x.y; o.z += x.z; o.w += x.w;
                }
                *reinterpret_cast<float4*>(&outf[base + c]) = o;
            }
        }
    } else {
        const float leak = fminf(fmaxf(leakp[0], 0.001f), 1000.f);
        const float* ka = kall + (size_t)b * KT;
        const float bv = ka[boff1 + m] + ka[boff2 + m];
        const float bg = ka[boff1 + 128 + m] + ka[boff2 + 128 + m];
        const size_t base = ((size_t)b * 128 + m) * NPIX + n0 + seg * 32;
        const float* ev = Es + m * EW + seg * 32;
        const float* eg = Es + (m + 128) * EW + seg * 32;
#pragma unroll
        for (int c = 0; c < 32; c += 4) {
            float4 x = *reinterpret_cast<const float4*>(&xold[base + c]);
            float4 o;
            { float v = ev[c+0] + bv, g = eg[c+0] + bg; o.x = x.x + leak * v / (1.f + __expf(-g)); }
            { float v = ev[c+1] + bv, g = eg[c+1] + bg; o.y = x.y + leak * v / (1.f + __expf(-g)); }
            { float v = ev[c+2] + bv, g = eg[c+2] + bg; o.z = x.z + leak * v / (1.f + __expf(-g)); }
            { float v = ev[c+3] + bv, g = eg[c+3] + bg; o.w = x.w + leak * v / (1.f + __expf(-g)); }
            *reinterpret_cast<float4*>(&outf[base + c]) = o;
        }
    }
}

// ======================================================================
// final 128->3 conv + clip
// ======================================================================
__global__ void __launch_bounds__(256) conv_img_kernel(
    const float* __restrict__ X, const float* __restrict__ W,
    const float* __restrict__ bias,
    float* __restrict__ out_img, float* __restrict__ out_raw)
{
    const int b = blockIdx.y, y0 = blockIdx.x * 4, tid = threadIdx.x;
    const int r = tid >> 6, x = tid & 63;
    __shared__ float sW[3 * 1152];
    __shared__ float sIn[6][66];
    for (int i = tid; i < 3 * 1152; i += 256) sW[i] = W[i];
    float acc[3] = {0.f, 0.f, 0.f};
    const float* Xb = X + (size_t)b * NF * NPIX;
    for (int ci = 0; ci < NF; ci++) {
        __syncthreads();
        for (int i = tid; i < 6 * 66; i += 256) {
            int ry = i / 66, cx = i - ry * 66;
            int gy = y0 - 1 + ry, gx = cx - 1;
            float v = 0.f;
            if ((unsigned)gy < 64u && (unsigned)gx < 64u)
                v = Xb[(size_t)ci * NPIX + gy * 64 + gx];
            sIn[ry][cx] = v;
        }
        __syncthreads();
        float in[9];
#pragma unroll
        for (int dy = 0; dy < 3; dy++)
#pragma unroll
            for (int dx = 0; dx < 3; dx++) in[dy * 3 + dx] = sIn[r + dy][x + dx];
#pragma unroll
        for (int o = 0; o < 3; o++)
#pragma unroll
            for (int j = 0; j < 9; j++)
                acc[o] = fmaf(in[j], sW[o * 1152 + ci * 9 + j], acc[o]);
    }
#pragma unroll
    for (int o = 0; o < 3; o++) {
        float v = acc[o] + bias[o];
        size_t idx = ((size_t)b * 3 + o) * NPIX + (size_t)(y0 + r) * 64 + x;
        out_raw[idx] = v;
        out_img[idx] = fminf(fmaxf(v, -1.f), 1.f);
    }
}

// ======================================================================
extern "C" void kernel_launch(void* const* d_in, const int* in_sizes, int n_in,
                              void* d_out, int out_size)
{
    const float* lat  = (const float*)d_in[0];
    const float* ca   = (const float*)d_in[1];
    const float* leak = (const float*)d_in[2];
    const float* hw   = (const float*)d_in[3];
    const float* hb   = (const float*)d_in[4];
    const float* rw1  = (const float*)d_in[5];
    const float* rb1  = (const float*)d_in[6];
    const float* rw2  = (const float*)d_in[7];
    const float* rb2  = (const float*)d_in[8];
    const float* iw   = (const float*)d_in[9];
    const float* ib   = (const float*)d_in[10];

    float* out = (float*)d_out;
    float* out_img = out;
    float* embs    = out + 98304;
    float* out_raw = out + 98304 + (size_t)17 * 4194304;

    float *kall, *c2;
    __half *pf, *h2f, *colf, *w1f, *w2f, *w3f, *r1f, *r2f;
    cudaGetSymbolAddress((void**)&kall, g_kall);
    cudaGetSymbolAddress((void**)&pf,  g_pf);
    cudaGetSymbolAddress((void**)&h2f, g_h2f);
    cudaGetSymbolAddress((void**)&w1f, g_w1f);
    cudaGetSymbolAddress((void**)&w2f, g_w2f);
    cudaGetSymbolAddress((void**)&w3f, g_w3f);
    cudaGetSymbolAddress((void**)&colf, g_colf);
    cudaGetSymbolAddress((void**)&r1f, g_rw1f);
    cudaGetSymbolAddress((void**)&r2f, g_rw2f);
    cudaGetSymbolAddress((void**)&c2, g_c2);

    // gemm<1>: stage = (128*40 + 32*136)*2B = 18944; 3x = 56832 < Es 67584
    // gemm<2>: stage = (256*40 + 32*72)*2B  = 25088; 3x = 75264 > Es 69632
    const int SM1 = 67584;
    const int SM2 = 75264;
    const int SMF = 104448;  // mlp12
    cudaFuncSetAttribute(gemm_wmma<1>, cudaFuncAttributeMaxDynamicSharedMemorySize, SM1);
    cudaFuncSetAttribute(gemm_wmma<2>, cudaFuncAttributeMaxDynamicSharedMemorySize, SM2);
    cudaFuncSetAttribute(mlp12_kernel, cudaFuncAttributeMaxDynamicSharedMemorySize, SMF);

    hyper_kernel<<<KT / 256, 256>>>(lat, hw, hb, kall);
    pack_rw_kernel<<<576, 256>>>(rw1, r1f);
    pack_rw_kernel<<<576, 256>>>(rw2, r2f);
    cudaMemcpyAsync(embs, ca, (size_t)4194304 * sizeof(float), cudaMemcpyDeviceToDevice);

    for (int t = 0; t < NCALLS; t++) {
        float* x  = embs + (size_t)t * 4194304;
        float* xn = x + 4194304;

        build_p_kernel<<<dim3(NF, NB), 256>>>(x, pf);
        mlp12_kernel<<<dim3(32, NB), 256, SMF>>>(w1f, w2f, pf, kall, h2f);
        gemm_wmma<2><<<dim3(64, NB), 256, SM2>>>(
            w3f, 512, h2f, 128, pf,
            kall, OFF_BOUT, OFF_BSH, nullptr, xn, nullptr, x, leak);
    }

    float* xf = embs + (size_t)NCALLS * 4194304;
    im2col_f32_kernel<<<18432, 256>>>(xf, colf);
    gemm_wmma<1><<<dim3(32, NB), 256, SM1>>>(
        r1f, 1152, colf, 1152, nullptr,
        nullptr, 0, 0, rb1, nullptr, pf, nullptr, nullptr);
    im2col_h_kernel<<<18432, 256>>>(pf, colf);
    gemm_wmma<1><<<dim3(32, NB), 256, SM1>>>(
        r2f, 1152, colf, 1152, nullptr,
        nullptr, 0, 0, rb2, c2, nullptr, xf, nullptr);
    conv_img_kernel<<<dim3(16, NB), 256>>>(c2, iw, ib, out_img, out_raw);
}

// round 17
// speedup vs baseline: 1.4980x; 1.0032x over previous
#include <cuda_runtime.h>
#include <cuda_fp16.h>
#include <mma.h>
#include <math.h>

using namespace nvcuda;

#define NB 8
#define NF 128
#define LATD 256
#define NPIX 4096
#define NCALLS 16
#define FIN 384
#define KT 197376

#define OFF_WIN  0
#define OFF_BIN  49152
#define OFF_WMID 49280
#define OFF_BMID 65664
#define OFF_WOUT 65792
#define OFF_BOUT 98560
#define OFF_WSH  98816
#define OFF_BSH  197120

#define COLSZ 4718592   // 1152 * 4096 (NOT a power of 2 — true division!)

// -------- scratch --------
__device__ __align__(16) float g_kall[NB * KT];
__device__ __align__(16) __half g_pf [NB * FIN * NPIX];
__device__ __align__(16) __half g_h2f[NB * NF * NPIX];
__device__ __align__(16) __half g_w1f[NB * 128 * 384];
__device__ __align__(16) __half g_w2f[NB * 128 * 128];
__device__ __align__(16) __half g_w3f[NB * 256 * 512];
__device__ __align__(16) __half g_colf[NB * 1152 * NPIX];
__device__ __align__(16) __half g_rw1f[NB * 147456];
__device__ __align__(16) __half g_rw2f[NB * 147456];
__device__ __align__(16) float g_c2[NB * NF * NPIX];

#define CP16(dst, src) \
    asm volatile("cp.async.cg.shared.global [%0], [%1], 16;\n" :: "r"(dst), "l"(src))
#define CP_COMMIT() asm volatile("cp.async.commit_group;\n" ::: "memory")
#define CP_WAIT(n)  asm volatile("cp.async.wait_group %0;\n" :: "n"(n) : "memory")

// ======================================================================
// hyper + pack fused (weights -> single fp16 plane)
// ======================================================================
__global__ void __launch_bounds__(256) hyper_kernel(
    const float* __restrict__ lat, const float* __restrict__ hw,
    const float* __restrict__ hb, float* __restrict__ kall)
{
    __shared__ float ls[NB * LATD];
    const int tid = threadIdx.x;
    for (int i = tid; i < NB * LATD; i += 256) ls[i] = lat[i];
    __syncthreads();
    const int n = blockIdx.x * 256 + tid;
    float acc[NB];
#pragma unroll
    for (int b = 0; b < NB; b++) acc[b] = 0.f;
    for (int k = 0; k < LATD; k++) {
        float w = hw[(size_t)k * KT + n];
#pragma unroll
        for (int b = 0; b < NB; b++) acc[b] = fmaf(ls[b * LATD + k], w, acc[b]);
    }
    const float bias = hb[n];

    float s = 1.f;
    int kind;
    size_t widx = 0;
    if (n < OFF_BIN)       { s = 0.05103103630798288f; kind = 0; widx = n; }
    else if (n < OFF_WMID) { kind = 3; }
    else if (n < OFF_BMID) { s = 0.08838834764831845f; kind = 1; widx = n - OFF_WMID; }
    else if (n < OFF_WOUT) { kind = 3; }
    else if (n < OFF_BOUT) {
        s = 0.08838834764831845f; kind = 2;
        int i = n - OFF_WOUT;
        widx = (size_t)(i >> 7) * 512 + (i & 127);
    } else if (n < OFF_WSH) { kind = 3; }
    else if (n < OFF_BSH) {
        s = 0.05103103630798288f; kind = 2;
        int i = n - OFF_WSH;
        widx = (size_t)(i / 384) * 512 + 128 + (i % 384);
    } else kind = 3;

#pragma unroll
    for (int b = 0; b < NB; b++) {
        float v = (acc[b] + bias) * s;
        if (kind == 3) {
            kall[(size_t)b * KT + n] = v;
        } else {
            __half h = __float2half_rn(v);
            if (kind == 0)      g_w1f[(size_t)b * 49152 + widx] = h;
            else if (kind == 1) g_w2f[(size_t)b * 16384 + widx] = h;
            else                g_w3f[(size_t)b * 131072 + widx] = h;
        }
    }
}

// ======================================================================
// pack res-conv weights -> single fp16 plane, replicated per batch
// ======================================================================
__global__ void __launch_bounds__(256) pack_rw_kernel(
    const float* __restrict__ w, __half* __restrict__ d)
{
    const int idx = blockIdx.x * 256 + threadIdx.x;
    const int o = idx / 1152, r = idx - o * 1152;
    const int t = r >> 7, c = r & 127;
    __half h = __float2half_rn(w[o * 1152 + c * 9 + t]);
#pragma unroll
    for (int b = 0; b < NB; b++)
        d[(size_t)b * 147456 + idx] = h;
}

// ======================================================================
// im2col, 8 px per thread, 16B stores
// ======================================================================
__global__ void __launch_bounds__(256) im2col_f32_kernel(
    const float* __restrict__ src, __half* __restrict__ d)
{
    const size_t idx = ((size_t)blockIdx.x * 256 + threadIdx.x) * 8;
    const int b = (int)(idx / COLSZ);
    const size_t r = idx - (size_t)b * COLSZ;
    const int k = (int)(r >> 12), px0 = (int)(r & 4095);
    const int tap = k >> 7, ch = k & 127;
    const int dy = tap / 3 - 1, dx = tap % 3 - 1;
    const int y = (px0 >> 6) + dy;
    const float* srow = src + (((size_t)b * 128 + ch) << 12) + y * 64;
    const bool yok = (unsigned)y < 64u;
    __half o[8];
#pragma unroll
    for (int i = 0; i < 8; i++) {
        int x = (px0 & 63) + i + dx;
        float v = (yok && (unsigned)x < 64u) ? srow[x] : 0.f;
        o[i] = __float2half_rn(v);
    }
    *reinterpret_cast<uint4*>(&d[idx]) = *reinterpret_cast<uint4*>(o);
}

__global__ void __launch_bounds__(256) im2col_h_kernel(
    const __half* __restrict__ src, __half* __restrict__ d)
{
    const size_t idx = ((size_t)blockIdx.x * 256 + threadIdx.x) * 8;
    const int b = (int)(idx / COLSZ);
    const size_t r = idx - (size_t)b * COLSZ;
    const int k = (int)(r >> 12), px0 = (int)(r & 4095);
    const int tap = k >> 7, ch = k & 127;
    const int dy = tap / 3 - 1, dx = tap % 3 - 1;
    const int y = (px0 >> 6) + dy;
    const __half* srow = src + (((size_t)b * 128 + ch) << 12) + y * 64;
    const bool yok = (unsigned)y < 64u;
    __half o[8];
#pragma unroll
    for (int i = 0; i < 8; i++) {
        int x = (px0 & 63) + i + dx;
        o[i] = (yok && (unsigned)x < 64u) ? srow[x] : __float2half_rn(0.f);
    }
    *reinterpret_cast<uint4*>(&d[idx]) = *reinterpret_cast<uint4*>(o);
}

// ======================================================================
// build_p -> single fp16 plane. Sobel results parked in smem (ssx/ssy)
// instead of 48 live registers (R16 version spilled). Bit-identical:
// same values, same accumulation order, same stores.
// dynamic smem: sp 4624 + ssx 4096 + ssy 4096 + red 48 + stats 6 floats
// ======================================================================
__global__ void __launch_bounds__(256) build_p_kernel(
    const float* __restrict__ X, __half* __restrict__ P)
{
    extern __shared__ __align__(16) float dsm[];
    float* sp    = dsm;            // 68*68
    float* ssx   = dsm + 4624;     // 4096
    float* ssy   = dsm + 8720;     // 4096
    float* red   = dsm + 12816;    // 8*6
    float* stats = dsm + 12864;    // 6

    const int c = blockIdx.x, b = blockIdx.y, tid = threadIdx.x;
    for (int i = tid; i < 68 * 68; i += 256) sp[i] = 0.f;
    __syncthreads();
    const float* Xp = X + ((size_t)b * NF + c) * NPIX;
    for (int i = tid; i < NPIX; i += 256) {
        int y = i >> 6, x = i & 63;
        sp[(y + 2) * 68 + (x + 2)] = Xp[i];
    }
    __syncthreads();
    const float C = 0.70710678118654752f;
    float s0 = 0.f, q0 = 0.f, s1 = 0.f, q1 = 0.f, s2 = 0.f, q2 = 0.f;
    for (int it = 0; it < 16; it++) {
        int pix = tid + it * 256;
        int y = pix >> 6, x = pix & 63;
        const float* B = &sp[y * 68 + x];
        float xv = B[2*68+2];
        float sx = C*(B[1*68+4]-B[1*68+0]) + 0.5f*(B[1*68+3]-B[1*68+1])
                 + (B[2*68+4]-B[2*68+0]) + C*(B[2*68+3]-B[2*68+1])
                 + C*(B[3*68+4]-B[3*68+0]) + 0.5f*(B[3*68+3]-B[3*68+1]);
        float sy = C*(B[4*68+1]-B[0*68+1]) + (B[4*68+2]-B[0*68+2])
                 + C*(B[4*68+3]-B[0*68+3])
                 + 0.5f*(B[3*68+1]-B[1*68+1]) + C*(B[3*68+2]-B[1*68+2])
                 + 0.5f*(B[3*68+3]-B[1*68+3]);
        ssx[pix] = sx;
        ssy[pix] = sy;
        s0 += xv; q0 = fmaf(xv, xv, q0);
        s1 += sx; q1 = fmaf(sx, sx, q1);
        s2 += sy; q2 = fmaf(sy, sy, q2);
    }
#pragma unroll
    for (int off = 16; off; off >>= 1) {
        s0 += __shfl_down_sync(~0u, s0, off); q0 += __shfl_down_sync(~0u, q0, off);
        s1 += __shfl_down_sync(~0u, s1, off); q1 += __shfl_down_sync(~0u, q1, off);
        s2 += __shfl_down_sync(~0u, s2, off); q2 += __shfl_down_sync(~0u, q2, off);
    }
    if ((tid & 31) == 0) {
        int w = tid >> 5;
        red[w*6+0]=s0; red[w*6+1]=q0; red[w*6+2]=s1;
        red[w*6+3]=q1; red[w*6+4]=s2; red[w*6+5]=q2;
    }
    __syncthreads();
    if (tid == 0) {
        float S[6] = {0,0,0,0,0,0};
        for (int w = 0; w < 8; w++) for (int j = 0; j < 6; j++) S[j] += red[w*6+j];
        const float invN = 1.f / 4096.f;
#pragma unroll
        for (int t3 = 0; t3 < 3; t3++) {
            float mu = S[2*t3] * invN;
            float var = fmaxf(S[2*t3+1] * invN - mu*mu, 0.f);
            stats[2*t3] = mu; stats[2*t3+1] = rsqrtf(var + 1e-5f);
        }
    }
    __syncthreads();
    const float mu0 = stats[0], in0 = stats[1], mu1 = stats[2], in1 = stats[3],
                mu2 = stats[4], in2 = stats[5];
    const size_t p0 = ((size_t)b * FIN + c) * NPIX;
    for (int it = 0; it < 16; it++) {
        int pix = tid + it * 256;
        int y = pix >> 6, x = pix & 63;
        float xv = sp[(y + 2) * 68 + (x + 2)];
        P[p0 + pix]                      = __float2half_rn((xv       - mu0) * in0);
        P[p0 + (size_t)NF*NPIX + pix]    = __float2half_rn((ssx[pix] - mu1) * in1);
        P[p0 + (size_t)2*NF*NPIX + pix]  = __float2half_rn((ssy[pix] - mu2) * in2);
    }
}

// ======================================================================
// FUSED g1+g2: h2 = relu(W2 @ relu(W1 @ p + b1) + b2), h1 lives in smem.
// ======================================================================
__global__ void __launch_bounds__(256, 2) mlp12_kernel(
    const __half* __restrict__ W1f, const __half* __restrict__ W2f,
    const __half* __restrict__ P, const float* __restrict__ kall,
    __half* __restrict__ H2out)
{
    constexpr int KCH = 16;
    constexpr int AW = 24;
    constexpr int BW = 136;
    constexpr int EW = 132;
    constexpr int A_ELEMS = 128 * AW;
    constexpr int BUF1 = A_ELEMS + KCH * BW;
    constexpr int BUF2 = A_ELEMS;

    extern __shared__ __align__(16) char sm[];
    __half* smH = (__half*)sm;
    float* Es = (float*)sm;
    __half* H = (__half*)(sm + 69632);

    const int tid = threadIdx.x;
    const int b = blockIdx.y;
    const int n0 = blockIdx.x * 128;
    const int wid = tid >> 5;
    const int wm = wid >> 1, wn = wid & 1;

    const __half* W1B = W1f + (size_t)b * 49152;
    const __half* W2B = W2f + (size_t)b * 16384;
    const __half* Pb = P + (size_t)b * FIN * NPIX;

    wmma::fragment<wmma::accumulator, 16, 16, 16, float> acc[2][4];
#pragma unroll
    for (int i = 0; i < 2; i++)
#pragma unroll
        for (int j = 0; j < 4; j++) wmma::fill_fragment(acc[i][j], 0.f);

    auto stage1 = [&](int kc, int s) {
        __half* Af = smH + (size_t)s * BUF1;
        __half* Bf = Af + A_ELEMS;
        {
            int m = tid >> 1, q = tid & 1;
            const __half* src = W1B + (size_t)m * 384 + kc + q * 8;
            unsigned d = (unsigned)__cvta_generic_to_shared(Af + m * AW + q * 8);
            CP16(d, src);
        }
        {
            int k = tid >> 4, c = (tid & 15) * 8;
            const __half* src = Pb + (size_t)(kc + k) * NPIX + n0 + c;
            unsigned d = (unsigned)__cvta_generic_to_shared(Bf + k * BW + c);
            CP16(d, src);
        }
        CP_COMMIT();
    };
    auto compute1 = [&](int s) {
        const __half* Af = smH + (size_t)s * BUF1;
        const __half* Bf = Af + A_ELEMS;
        wmma::fragment<wmma::matrix_a, 16, 16, 16, __half, wmma::row_major> af[2];
        wmma::fragment<wmma::matrix_b, 16, 16, 16, __half, wmma::row_major> bf[4];
#pragma unroll
        for (int i = 0; i < 2; i++)
            wmma::load_matrix_sync(af[i], Af + (wm * 32 + i * 16) * AW, AW);
#pragma unroll
        for (int j = 0; j < 4; j++)
            wmma::load_matrix_sync(bf[j], Bf + wn * 64 + j * 16, BW);
#pragma unroll
        for (int i = 0; i < 2; i++)
#pragma unroll
            for (int j = 0; j < 4; j++)
                wmma::mma_sync(acc[i][j], af[i], bf[j], acc[i][j]);
    };

    {
        const int nch = 24;
        stage1(0, 0);
        stage1(KCH, 1);
        CP_WAIT(1);
        __syncthreads();
        for (int ic = 0; ic < nch; ic++) {
            compute1(ic % 3);
            if (ic + 2 < nch) {
                stage1((ic + 2) * KCH, (ic + 2) % 3);
                CP_WAIT(1);
            } else {
                CP_WAIT(0);
            }
            __syncthreads();
        }
    }
#pragma unroll
    for (int i = 0; i < 2; i++)
#pragma unroll
        for (int j = 0; j < 4; j++)
            wmma::store_matrix_sync(Es + (wm * 32 + i * 16) * EW + wn * 64 + j * 16,
                                    acc[i][j], EW, wmma::mem_row_major);
    __syncthreads();
    {
        const int m = tid >> 1, seg = tid & 1;
        const float bias1 = kall[(size_t)b * KT + OFF_BIN + m];
        const float* er = Es + m * EW + seg * 64;
        __half* hr = H + m * BW + seg * 64;
#pragma unroll
        for (int c = 0; c < 64; c += 2) {
            __half2 o;
            o.x = __float2half_rn(fmaxf(er[c + 0] + bias1, 0.f));
            o.y = __float2half_rn(fmaxf(er[c + 1] + bias1, 0.f));
            *reinterpret_cast<__half2*>(&hr[c]) = o;
        }
    }
    __syncthreads();

#pragma unroll
    for (int i = 0; i < 2; i++)
#pragma unroll
        for (int j = 0; j < 4; j++) wmma::fill_fragment(acc[i][j], 0.f);

    auto stage2 = [&](int kc, int s) {
        __half* Af = smH + (size_t)s * BUF2;
        int m = tid >> 1, q = tid & 1;
        const __half* src = W2B + (size_t)m * 128 + kc + q * 8;
        unsigned d = (unsigned)__cvta_generic_to_shared(Af + m * AW + q * 8);
        CP16(d, src);
        CP_COMMIT();
    };
    auto compute2 = [&](int kc, int s) {
        const __half* Af = smH + (size_t)s * BUF2;
        wmma::fragment<wmma::matrix_a, 16, 16, 16, __half, wmma::row_major> af[2];
        wmma::fragment<wmma::matrix_b, 16, 16, 16, __half, wmma::row_major> bf[4];
#pragma unroll
        for (int i = 0; i < 2; i++)
            wmma::load_matrix_sync(af[i], Af + (wm * 32 + i * 16) * AW, AW);
#pragma unroll
        for (int j = 0; j < 4; j++)
            wmma::load_matrix_sync(bf[j], H + kc * BW + wn * 64 + j * 16, BW);
#pragma unroll
        for (int i = 0; i < 2; i++)
#pragma unroll
            for (int j = 0; j < 4; j++)
                wmma::mma_sync(acc[i][j], af[i], bf[j], acc[i][j]);
    };

    {
        const int nch = 8;
        stage2(0, 0);
        stage2(KCH, 1);
        CP_WAIT(1);
        __syncthreads();
        for (int ic = 0; ic < nch; ic++) {
            compute2(ic * KCH, ic % 3);
            if (ic + 2 < nch) {
                stage2((ic + 2) * KCH, (ic + 2) % 3);
                CP_WAIT(1);
            } else {
                CP_WAIT(0);
            }
            __syncthreads();
        }
    }
#pragma unroll
    for (int i = 0; i < 2; i++)
#pragma unroll
        for (int j = 0; j < 4; j++)
            wmma::store_matrix_sync(Es + (wm * 32 + i * 16) * EW + wn * 64 + j * 16,
                                    acc[i][j], EW, wmma::mem_row_major);
    __syncthreads();
    {
        const int m = tid >> 1, seg = tid & 1;
        const float bias2 = kall[(size_t)b * KT + OFF_BMID + m];
        const size_t base = ((size_t)b * 128 + m) * NPIX + n0 + seg * 64;
        const float* er = Es + m * EW + seg * 64;
#pragma unroll
        for (int c = 0; c < 64; c += 2) {
            __half2 o;
            o.x = __float2half_rn(fmaxf(er[c + 0] + bias2, 0.f));
            o.y = __float2half_rn(fmaxf(er[c + 1] + bias2, 0.f));
            *reinterpret_cast<__half2*>(&H2out[base + c]) = o;
        }
    }
}

// ======================================================================
// wmma fp16 GEMM: single term, 3-stage / 1 sync, KCH=32.
// MBLKS=1: conv tail; MBLKS=2: g3 gated update
// ======================================================================
template<int MBLKS>
__global__ void __launch_bounds__(256, 2) gemm_wmma(
    const __half* __restrict__ Wf, int Ktot,
    const __half* __restrict__ B1, int K1, const __half* __restrict__ B2,
    const float* __restrict__ kall, int boff1, int boff2,
    const float* __restrict__ bias_dir,
    float* __restrict__ outf, __half* __restrict__ outh,
    const float* __restrict__ xold, const float* __restrict__ leakp)
{
    constexpr int MT = MBLKS * 128;
    constexpr int NT = 128 / MBLKS;
    constexpr int KCH = 32;
    constexpr int KK = 2;
    constexpr int AP = 4;
    constexpr int AW = 40;
    constexpr int BW = (MBLKS == 1) ? 136 : 72;
    constexpr int EW = NT + 4;
    constexpr int BUFE = MT * AW + KCH * BW;

    extern __shared__ __align__(16) char sm[];
    __half* smB = (__half*)sm;
    float* Es = (float*)sm;

    const int tid = threadIdx.x;
    const int b = blockIdx.y;
    const int n0 = blockIdx.x * NT;
    const int wid = tid >> 5;
    const int wm = (MBLKS == 1) ? (wid >> 1) : wid;
    const int wn = (MBLKS == 1) ? (wid & 1) : 0;

    const __half* WB = Wf + (size_t)b * MT * Ktot;

    wmma::fragment<wmma::accumulator, 16, 16, 16, float> acc[2][4];
#pragma unroll
    for (int i = 0; i < 2; i++)
#pragma unroll
        for (int j = 0; j < 4; j++) wmma::fill_fragment(acc[i][j], 0.f);

    auto stage = [&](int kc, int s) {
        __half* Af = smB + (size_t)s * BUFE;
        __half* Bf = Af + MT * AW;
#pragma unroll
        for (int i = tid; i < MT * AP; i += 256) {
            int m = i / AP, q = i - m * AP;
            const __half* src = WB + (size_t)m * Ktot + kc + q * 8;
            unsigned d = (unsigned)__cvta_generic_to_shared(Af + m * AW + q * 8);
            CP16(d, src);
        }
        const __half* sf; int ch0;
        if (kc < K1) { sf = B1 + (size_t)b * K1 * NPIX; ch0 = kc; }
        else { sf = B2 + (size_t)b * (Ktot - K1) * NPIX; ch0 = kc - K1; }
        constexpr int NC8 = NT / 8;
#pragma unroll
        for (int i = tid; i < KCH * NC8; i += 256) {
            int k = i / NC8, c = (i - k * NC8) * 8;
            const __half* src = sf + (size_t)(ch0 + k) * NPIX + n0 + c;
            unsigned d = (unsigned)__cvta_generic_to_shared(Bf + k * BW + c);
            CP16(d, src);
        }
        CP_COMMIT();
    };

    auto compute = [&](int s) {
        const __half* Af = smB + (size_t)s * BUFE;
        const __half* Bf = Af + MT * AW;
#pragma unroll
        for (int kk = 0; kk < KK; kk++) {
            wmma::fragment<wmma::matrix_a, 16, 16, 16, __half, wmma::row_major> af[2];
            wmma::fragment<wmma::matrix_b, 16, 16, 16, __half, wmma::row_major> bf[4];
#pragma unroll
            for (int i = 0; i < 2; i++)
                wmma::load_matrix_sync(af[i], Af + (wm * 32 + i * 16) * AW + kk * 16, AW);
#pragma unroll
            for (int j = 0; j < 4; j++)
                wmma::load_matrix_sync(bf[j], Bf + kk * 16 * BW + wn * 64 + j * 16, BW);
#pragma unroll
            for (int i = 0; i < 2; i++)
#pragma unroll
                for (int j = 0; j < 4; j++)
                    wmma::mma_sync(acc[i][j], af[i], bf[j], acc[i][j]);
        }
    };

    const int nch = Ktot / KCH;
    stage(0, 0);
    stage(KCH, 1);
    CP_WAIT(1);
    __syncthreads();
    for (int ic = 0; ic < nch; ic++) {
        compute(ic % 3);
        if (ic + 2 < nch) {
            stage((ic + 2) * KCH, (ic + 2) % 3);
            CP_WAIT(1);
        } else {
            CP_WAIT(0);
        }
        __syncthreads();
    }

#pragma unroll
    for (int i = 0; i < 2; i++)
#pragma unroll
        for (int j = 0; j < 4; j++)
            wmma::store_matrix_sync(Es + (wm * 32 + i * 16) * EW + wn * 64 + j * 16,
                                    acc[i][j], EW, wmma::mem_row_major);
    __syncthreads();

    const int m = tid >> 1, seg = tid & 1;
    if (MBLKS == 1) {
        const float bias = kall ? kall[(size_t)b * KT + boff1 + m] : bias_dir[m];
        const size_t base = ((size_t)b * 128 + m) * NPIX + n0 + seg * 64;
        const float* er = Es + m * EW + seg * 64;
        if (outh) {
#pragma unroll
            for (int c = 0; c < 64; c += 2) {
                __half2 o;
                o.x = __float2half_rn(fmaxf(er[c + 0] + bias, 0.f));
                o.y = __float2half_rn(fmaxf(er[c + 1] + bias, 0.f));
                *reinterpret_cast<__half2*>(&outh[base + c]) = o;
            }
        } else {
#pragma unroll
            for (int c = 0; c < 64; c += 4) {
                float4 o;
                o.x = er[c+0] + bias; o.y = er[c+1] + bias;
                o.z = er[c+2] + bias; o.w = er[c+3] + bias;
                if (xold) {
                    float4 x = *reinterpret_cast<const float4*>(&xold[base + c]);
                    o.x += x.x; o.y += x.y; o.z += x.z; o.w += x.w;
                }
                *reinterpret_cast<float4*>(&outf[base + c]) = o;
            }
        }
    } else {
        const float leak = fminf(fmaxf(leakp[0], 0.001f), 1000.f);
        const float* ka = kall + (size_t)b * KT;
        const float bv = ka[boff1 + m] + ka[boff2 + m];
        const float bg = ka[boff1 + 128 + m] + ka[boff2 + 128 + m];
        const size_t base = ((size_t)b * 128 + m) * NPIX + n0 + seg * 32;
        const float* ev = Es + m * EW + seg * 32;
        const float* eg = Es + (m + 128) * EW + seg * 32;
#pragma unroll
        for (int c = 0; c < 32; c += 4) {
            float4 x = *reinterpret_cast<const float4*>(&xold[base + c]);
            float4 o;
            { float v = ev[c+0] + bv, g = eg[c+0] + bg; o.x = x.x + leak * v / (1.f + __expf(-g)); }
            { float v = ev[c+1] + bv, g = eg[c+1] + bg; o.y = x.y + leak * v / (1.f + __expf(-g)); }
            { float v = ev[c+2] + bv, g = eg[c+2] + bg; o.z = x.z + leak * v / (1.f + __expf(-g)); }
            { float v = ev[c+3] + bv, g = eg[c+3] + bg; o.w = x.w + leak * v / (1.f + __expf(-g)); }
            *reinterpret_cast<float4*>(&outf[base + c]) = o;
        }
    }
}

// ======================================================================
// final 128->3 conv + clip
// ======================================================================
__global__ void __launch_bounds__(256) conv_img_kernel(
    const float* __restrict__ X, const float* __restrict__ W,
    const float* __restrict__ bias,
    float* __restrict__ out_img, float* __restrict__ out_raw)
{
    const int b = blockIdx.y, y0 = blockIdx.x * 4, tid = threadIdx.x;
    const int r = tid >> 6, x = tid & 63;
    __shared__ float sW[3 * 1152];
    __shared__ float sIn[6][66];
    for (int i = tid; i < 3 * 1152; i += 256) sW[i] = W[i];
    float acc[3] = {0.f, 0.f, 0.f};
    const float* Xb = X + (size_t)b * NF * NPIX;
    for (int ci = 0; ci < NF; ci++) {
        __syncthreads();
        for (int i = tid; i < 6 * 66; i += 256) {
            int ry = i / 66, cx = i - ry * 66;
            int gy = y0 - 1 + ry, gx = cx - 1;
            float v = 0.f;
            if ((unsigned)gy < 64u && (unsigned)gx < 64u)
                v = Xb[(size_t)ci * NPIX + gy * 64 + gx];
            sIn[ry][cx] = v;
        }
        __syncthreads();
        float in[9];
#pragma unroll
        for (int dy = 0; dy < 3; dy++)
#pragma unroll
            for (int dx = 0; dx < 3; dx++) in[dy * 3 + dx] = sIn[r + dy][x + dx];
#pragma unroll
        for (int o = 0; o < 3; o++)
#pragma unroll
            for (int j = 0; j < 9; j++)
                acc[o] = fmaf(in[j], sW[o * 1152 + ci * 9 + j], acc[o]);
    }
#pragma unroll
    for (int o = 0; o < 3; o++) {
        float v = acc[o] + bias[o];
        size_t idx = ((size_t)b * 3 + o) * NPIX + (size_t)(y0 + r) * 64 + x;
        out_raw[idx] = v;
        out_img[idx] = fminf(fmaxf(v, -1.f), 1.f);
    }
}

// ======================================================================
extern "C" void kernel_launch(void* const* d_in, const int* in_sizes, int n_in,
                              void* d_out, int out_size)
{
    const float* lat  = (const float*)d_in[0];
    const float* ca   = (const float*)d_in[1];
    const float* leak = (const float*)d_in[2];
    const float* hw   = (const float*)d_in[3];
    const float* hb   = (const float*)d_in[4];
    const float* rw1  = (const float*)d_in[5];
    const float* rb1  = (const float*)d_in[6];
    const float* rw2  = (const float*)d_in[7];
    const float* rb2  = (const float*)d_in[8];
    const float* iw   = (const float*)d_in[9];
    const float* ib   = (const float*)d_in[10];

    float* out = (float*)d_out;
    float* out_img = out;
    float* embs    = out + 98304;
    float* out_raw = out + 98304 + (size_t)17 * 4194304;

    float *kall, *c2;
    __half *pf, *h2f, *colf, *w1f, *w2f, *w3f, *r1f, *r2f;
    cudaGetSymbolAddress((void**)&kall, g_kall);
    cudaGetSymbolAddress((void**)&pf,  g_pf);
    cudaGetSymbolAddress((void**)&h2f, g_h2f);
    cudaGetSymbolAddress((void**)&w1f, g_w1f);
    cudaGetSymbolAddress((void**)&w2f, g_w2f);
    cudaGetSymbolAddress((void**)&w3f, g_w3f);
    cudaGetSymbolAddress((void**)&colf, g_colf);
    cudaGetSymbolAddress((void**)&r1f, g_rw1f);
    cudaGetSymbolAddress((void**)&r2f, g_rw2f);
    cudaGetSymbolAddress((void**)&c2, g_c2);

    const int SM1 = 67584;   // gemm<1>
    const int SM2 = 75264;   // gemm<2>
    const int SMF = 104448;  // mlp12
    const int SMP = 51712;   // build_p: 12870 floats
    cudaFuncSetAttribute(gemm_wmma<1>, cudaFuncAttributeMaxDynamicSharedMemorySize, SM1);
    cudaFuncSetAttribute(gemm_wmma<2>, cudaFuncAttributeMaxDynamicSharedMemorySize, SM2);
    cudaFuncSetAttribute(mlp12_kernel, cudaFuncAttributeMaxDynamicSharedMemorySize, SMF);
    cudaFuncSetAttribute(build_p_kernel, cudaFuncAttributeMaxDynamicSharedMemorySize, SMP);

    hyper_kernel<<<KT / 256, 256>>>(lat, hw, hb, kall);
    pack_rw_kernel<<<576, 256>>>(rw1, r1f);
    pack_rw_kernel<<<576, 256>>>(rw2, r2f);
    cudaMemcpyAsync(embs, ca, (size_t)4194304 * sizeof(float), cudaMemcpyDeviceToDevice);

    for (int t = 0; t < NCALLS; t++) {
        float* x  = embs + (size_t)t * 4194304;
        float* xn = x + 4194304;

        build_p_kernel<<<dim3(NF, NB), 256, SMP>>>(x, pf);
        mlp12_kernel<<<dim3(32, NB), 256, SMF>>>(w1f, w2f, pf, kall, h2f);
        gemm_wmma<2><<<dim3(64, NB), 256, SM2>>>(
            w3f, 512, h2f, 128, pf,
            kall, OFF_BOUT, OFF_BSH, nullptr, xn, nullptr, x, leak);
    }

    float* xf = embs + (size_t)NCALLS * 4194304;
    im2col_f32_kernel<<<18432, 256>>>(xf, colf);
    gemm_wmma<1><<<dim3(32, NB), 256, SM1>>>(
        r1f, 1152, colf, 1152, nullptr,
        nullptr, 0, 0, rb1, nullptr, pf, nullptr, nullptr);
    im2col_h_kernel<<<18432, 256>>>(pf, colf);
    gemm_wmma<1><<<dim3(32, NB), 256, SM1>>>(
        r2f, 1152, colf, 1152, nullptr,
        nullptr, 0, 0, rb2, c2, nullptr, xf, nullptr);
    conv_img_kernel<<<dim3(16, NB), 256>>>(c2, iw, ib, out_img, out_raw);
}